// round 8
// baseline (speedup 1.0000x reference)
#include <cuda_runtime.h>
#include <cstdint>
#include <cstddef>

// ============================================================================
// interAUGraphConv, GB300 (compute_103 PTX => no tcgen05; mma.sync tf32)
//
//   GEMM1: T[8192,1024]   = adj @ (w/17)       -- fp32 SIMT, sequential-k
//   GEMM2: pre[8192,8192] = T @ inputs         -- 3xTF32 mma.sync, PRE-SPLIT
//   out = (0.6<pre<=1 ? pre : 1)/prob[row], mask = pre>0.6
//
// Two-term split is exact (hi = tf32(x), lo = x-hi, hi+lo == x bitwise), so
// Th/Tl and Bh/Bl are stored pre-split; gemm2's hot loop has NO cvt/sub.
// Elements with |pre-0.6| < DELTA are recomputed sequential-k fp32 (operands
// reconstructed exactly as hi+lo) by the fixup pass.
// ============================================================================

static const int KDIM = 1024;
static const int BM = 128, BN = 128, BK = 16;
static const int PAD = 20;
static const int TILE_WORDS = 128 * PAD;           // 2560 words per tile
static const int STAGE_WORDS = 4 * TILE_WORDS;     // Ah, Al, Bh, Bl
static const int STAGE_B = STAGE_WORDS * 4;        // 40960 bytes
static const int SMEM_TOTAL = 3 * STAGE_B;         // 122880

static const unsigned FIX_CAP = 1u << 22;
#define DELTA 2.0e-3f

// ---- device scratch ----
__device__ float gTh[(size_t)8192 * 1024];    // hi(T)
__device__ float gTl[(size_t)8192 * 1024];    // lo(T)
__device__ float gBh[(size_t)8192 * 1024];    // hi(inputs^T)
__device__ float gBl[(size_t)8192 * 1024];    // lo(inputs^T)
__device__ unsigned gFixCnt;
__device__ unsigned gFix[FIX_CAP];

// ---------------------------------------------------------------------------
__device__ __forceinline__ float tf32r(float x) {
    float r;
    asm("cvt.rna.tf32.f32 %0, %1;" : "=f"(r) : "f"(x));
    return r;
}
__device__ __forceinline__ uint32_t smem_u32(const void* p) {
    uint32_t a;
    asm("{ .reg .u64 t; cvta.to.shared.u64 t, %1; cvt.u32.u64 %0, t; }" : "=r"(a) : "l"(p));
    return a;
}
#define CP_ASYNC16(saddr, gptr) \
    asm volatile("cp.async.cg.shared.global [%0], [%1], 16;" :: "r"(saddr), "l"(gptr))
#define CP_COMMIT() asm volatile("cp.async.commit_group;" ::: "memory")
#define CP_WAIT1()  asm volatile("cp.async.wait_group 1;" ::: "memory")

#define MMA_TF32(d, a, b)                                                   \
    asm volatile(                                                           \
        "mma.sync.aligned.m16n8k8.row.col.f32.tf32.tf32.f32 "               \
        "{%0,%1,%2,%3}, {%4,%5,%6,%7}, {%8,%9}, {%0,%1,%2,%3};"             \
        : "+f"((d)[0]), "+f"((d)[1]), "+f"((d)[2]), "+f"((d)[3])            \
        : "r"((a)[0]), "r"((a)[1]), "r"((a)[2]), "r"((a)[3]),               \
          "r"((b)[0]), "r"((b)[1]))

// ---------------------------------------------------------------------------
// transpose + split: inputs [1024, 8192] -> gBh/gBl [8192, 1024]
// ---------------------------------------------------------------------------
__global__ __launch_bounds__(256) void tkern(const float* __restrict__ in, int N) {
    __shared__ float t[32][33];
    int n0 = blockIdx.x * 32, k0 = blockIdx.y * 32;
    int tx = threadIdx.x, ty = threadIdx.y;    // (32, 8)
    #pragma unroll
    for (int p = 0; p < 4; p++)
        t[ty + p * 8][tx] = in[(size_t)(k0 + ty + p * 8) * N + n0 + tx];
    __syncthreads();
    #pragma unroll
    for (int p = 0; p < 4; p++) {
        float x  = t[tx][ty + p * 8];
        float hi = tf32r(x);
        size_t o = (size_t)(n0 + ty + p * 8) * KDIM + k0 + tx;
        gBh[o] = hi;
        gBl[o] = x - hi;
    }
}

__global__ void zkern() { gFixCnt = 0; }

// ---------------------------------------------------------------------------
// GEMM1: fp32 SIMT sequential-k; epilogue stores split T -> gTh/gTl
// ---------------------------------------------------------------------------
__global__ __launch_bounds__(256, 2)
void sgemm1(const float* __restrict__ A, const float* __restrict__ B)
{
    __shared__ float As[BK][BM + 4];
    __shared__ float Bs[BK][BN];

    const int tid = threadIdx.x;
    const int tx  = tid & 15;
    const int ty  = tid >> 4;
    const int bm  = blockIdx.y * BM;
    const int bn  = blockIdx.x * BN;
    const int K = 1024, N = 1024;
    const float bscale = 1.0f / 17.0f;

    const float* Ab = A + (size_t)bm * K;
    const float* Bb = B + bn;

    float acc[8][8];
    #pragma unroll
    for (int i = 0; i < 8; i++)
        #pragma unroll
        for (int j = 0; j < 8; j++) acc[i][j] = 0.0f;

    for (int k0 = 0; k0 < K; k0 += BK) {
        #pragma unroll
        for (int l = 0; l < 2; l++) {
            int i = tid + l * 256, row = i >> 2, kc = (i & 3) * 4;
            float4 v = *(const float4*)(Ab + (size_t)row * K + (k0 + kc));
            As[kc + 0][row] = v.x; As[kc + 1][row] = v.y;
            As[kc + 2][row] = v.z; As[kc + 3][row] = v.w;
        }
        #pragma unroll
        for (int l = 0; l < 2; l++) {
            int i = tid + l * 256, row = i >> 5, col = (i & 31) * 4;
            float4 v = *(const float4*)(Bb + (size_t)(k0 + row) * N + col);
            v.x *= bscale; v.y *= bscale; v.z *= bscale; v.w *= bscale;
            *(float4*)&Bs[row][col] = v;
        }
        __syncthreads();
        #pragma unroll
        for (int k = 0; k < BK; k++) {
            float regM[8], regN[8];
            *(float4*)&regM[0] = *(const float4*)&As[k][ty * 8];
            *(float4*)&regM[4] = *(const float4*)&As[k][ty * 8 + 4];
            *(float4*)&regN[0] = *(const float4*)&Bs[k][tx * 8];
            *(float4*)&regN[4] = *(const float4*)&Bs[k][tx * 8 + 4];
            #pragma unroll
            for (int i = 0; i < 8; i++)
                #pragma unroll
                for (int j = 0; j < 8; j++)
                    acc[i][j] += regM[i] * regN[j];
        }
        __syncthreads();
    }
    #pragma unroll
    for (int i = 0; i < 8; i++) {
        int r = bm + ty * 8 + i;
        #pragma unroll
        for (int jj = 0; jj < 8; jj += 4) {
            float4 hv, lv;
            #pragma unroll
            for (int q = 0; q < 4; q++) {
                float x  = acc[i][jj + q];
                float hi = tf32r(x);
                ((float*)&hv)[q] = hi;
                ((float*)&lv)[q] = x - hi;
            }
            size_t off = (size_t)r * N + (bn + tx * 8 + jj);
            *(float4*)(gTh + off) = hv;
            *(float4*)(gTl + off) = lv;
        }
    }
}

// ---------------------------------------------------------------------------
// GEMM2: 3xTF32 mma.sync on pre-split data + flagging epilogue
// ---------------------------------------------------------------------------
__device__ __forceinline__ void fill_stage2(uint32_t sm, int buf, int kc,
                                            int bm, int bn, int tid) {
    uint32_t base = sm + buf * STAGE_B;
    #pragma unroll
    for (int t = 0; t < 2; t++) {
        int idx = tid + t * 256;
        int row = idx >> 2, q = idx & 3;
        uint32_t so = (uint32_t)(row * PAD + q * 4) * 4;
        size_t ga = (size_t)(bm + row) * KDIM + kc * BK + q * 4;
        size_t gb = (size_t)(bn + row) * KDIM + kc * BK + q * 4;
        CP_ASYNC16(base + so,                     gTh + ga);
        CP_ASYNC16(base + TILE_WORDS * 4 + so,    gTl + ga);
        CP_ASYNC16(base + TILE_WORDS * 8 + so,    gBh + gb);
        CP_ASYNC16(base + TILE_WORDS * 12 + so,   gBl + gb);
    }
}

__global__ __launch_bounds__(256, 1)
void gemm2(float* __restrict__ outp, float* __restrict__ maskp,
           const float* __restrict__ prob)
{
    extern __shared__ float smem[];
    uint32_t sm = smem_u32(smem);

    const int tid  = threadIdx.x;
    const int w    = tid >> 5;
    const int lane = tid & 31;
    const int g    = lane >> 2;
    const int tg   = lane & 3;
    const int warpM = (w & 1) * 64;
    const int warpN = (w >> 1) * 32;
    const int bm = blockIdx.y * BM;
    const int bn = blockIdx.x * BN;

    float d[4][4][4];
    #pragma unroll
    for (int i = 0; i < 4; i++)
        #pragma unroll
        for (int j = 0; j < 4; j++)
            #pragma unroll
            for (int c = 0; c < 4; c++) d[i][j][c] = 0.0f;

    fill_stage2(sm, 0, 0, bm, bn, tid); CP_COMMIT();
    fill_stage2(sm, 1, 1, bm, bn, tid); CP_COMMIT();

    const int NCH = KDIM / BK;   // 64
    for (int i = 0; i < NCH; i++) {
        CP_WAIT1();
        __syncthreads();
        int j = i + 2;
        if (j < NCH) fill_stage2(sm, j % 3, j, bm, bn, tid);
        CP_COMMIT();

        const float* Ash = smem + (i % 3) * STAGE_WORDS;
        const float* Asl = Ash + TILE_WORDS;
        const float* Bsh = Ash + 2 * TILE_WORDS;
        const float* Bsl = Ash + 3 * TILE_WORDS;

        #pragma unroll
        for (int ks = 0; ks < 2; ks++) {
            uint32_t ah[4][4], al[4][4], bh[4][2], bl[4][2];
            #pragma unroll
            for (int mt = 0; mt < 4; mt++) {
                int m = warpM + mt * 16 + g;
                int o0 = m * PAD + ks * 8 + tg;
                int o1 = (m + 8) * PAD + ks * 8 + tg;
                ah[mt][0] = __float_as_uint(Ash[o0]);
                ah[mt][1] = __float_as_uint(Ash[o1]);
                ah[mt][2] = __float_as_uint(Ash[o0 + 4]);
                ah[mt][3] = __float_as_uint(Ash[o1 + 4]);
                al[mt][0] = __float_as_uint(Asl[o0]);
                al[mt][1] = __float_as_uint(Asl[o1]);
                al[mt][2] = __float_as_uint(Asl[o0 + 4]);
                al[mt][3] = __float_as_uint(Asl[o1 + 4]);
            }
            #pragma unroll
            for (int nt = 0; nt < 4; nt++) {
                int n = warpN + nt * 8 + g;
                int o = n * PAD + ks * 8 + tg;
                bh[nt][0] = __float_as_uint(Bsh[o]);
                bh[nt][1] = __float_as_uint(Bsh[o + 4]);
                bl[nt][0] = __float_as_uint(Bsl[o]);
                bl[nt][1] = __float_as_uint(Bsl[o + 4]);
            }
            #pragma unroll
            for (int mt = 0; mt < 4; mt++)
                #pragma unroll
                for (int nt = 0; nt < 4; nt++) MMA_TF32(d[mt][nt], ah[mt], bh[nt]);
            #pragma unroll
            for (int mt = 0; mt < 4; mt++)
                #pragma unroll
                for (int nt = 0; nt < 4; nt++) MMA_TF32(d[mt][nt], al[mt], bh[nt]);
            #pragma unroll
            for (int mt = 0; mt < 4; mt++)
                #pragma unroll
                for (int nt = 0; nt < 4; nt++) MMA_TF32(d[mt][nt], ah[mt], bl[nt]);
        }
        __syncthreads();
    }

    // ---- epilogue: activation + mask + near-threshold flagging ----
    #pragma unroll
    for (int mt = 0; mt < 4; mt++) {
        int r0 = bm + warpM + mt * 16 + g;
        int r1 = r0 + 8;
        float rp0 = 1.0f / prob[r0];
        float rp1 = 1.0f / prob[r1];
        #pragma unroll
        for (int nt = 0; nt < 4; nt++) {
            int c = bn + warpN + nt * 8 + tg * 2;
            float2 o0, o1, m0, m1;
            #pragma unroll
            for (int q = 0; q < 4; q++) {
                float pre = d[mt][nt][q];
                int   rr  = (q < 2) ? r0 : r1;
                int   cc  = c + (q & 1);
                bool  gt  = pre > 0.6f;
                float act = (gt && pre <= 1.0f) ? pre : 1.0f;
                float rv  = act * ((q < 2) ? rp0 : rp1);
                float mv  = gt ? 1.0f : 0.0f;
                if (q == 0) { o0.x = rv; m0.x = mv; }
                else if (q == 1) { o0.y = rv; m0.y = mv; }
                else if (q == 2) { o1.x = rv; m1.x = mv; }
                else { o1.y = rv; m1.y = mv; }
                if (fabsf(pre - 0.6f) < DELTA) {
                    unsigned idx = atomicAdd(&gFixCnt, 1u);
                    if (idx < FIX_CAP)
                        gFix[idx] = ((unsigned)rr << 13) | (unsigned)cc;
                }
            }
            *(float2*)(outp  + (size_t)r0 * 8192 + c) = o0;
            *(float2*)(outp  + (size_t)r1 * 8192 + c) = o1;
            *(float2*)(maskp + (size_t)r0 * 8192 + c) = m0;
            *(float2*)(maskp + (size_t)r1 * 8192 + c) = m1;
        }
    }
}

// ---------------------------------------------------------------------------
// fixup: recompute flagged elements, sequential-k fp32 (operands = hi+lo exact)
// ---------------------------------------------------------------------------
__global__ __launch_bounds__(256)
void fixup(float* __restrict__ outp, float* __restrict__ maskp,
           const float* __restrict__ prob)
{
    unsigned cnt = gFixCnt;
    if (cnt > FIX_CAP) cnt = FIX_CAP;
    unsigned stride = gridDim.x * blockDim.x;
    for (unsigned i = blockIdx.x * blockDim.x + threadIdx.x; i < cnt; i += stride) {
        unsigned e = gFix[i];
        int m = e >> 13;
        int n = e & 8191;
        const float4* ath = (const float4*)(gTh + (size_t)m * KDIM);
        const float4* atl = (const float4*)(gTl + (size_t)m * KDIM);
        const float4* bth = (const float4*)(gBh + (size_t)n * KDIM);
        const float4* btl = (const float4*)(gBl + (size_t)n * KDIM);
        float s = 0.0f;
        #pragma unroll 4
        for (int k = 0; k < KDIM / 4; k++) {
            float4 ah = ath[k], al = atl[k], bh = bth[k], bl = btl[k];
            s = fmaf(ah.x + al.x, bh.x + bl.x, s);
            s = fmaf(ah.y + al.y, bh.y + bl.y, s);
            s = fmaf(ah.z + al.z, bh.z + bl.z, s);
            s = fmaf(ah.w + al.w, bh.w + bl.w, s);
        }
        bool  gt  = s > 0.6f;
        float act = (gt && s <= 1.0f) ? s : 1.0f;
        size_t off = (size_t)m * 8192 + n;
        outp[off]  = act * (1.0f / prob[m]);
        maskp[off] = gt ? 1.0f : 0.0f;
    }
}

// ---------------------------------------------------------------------------
extern "C" void kernel_launch(void* const* d_in, const int* in_sizes, int n_in,
                              void* d_out, int out_size)
{
    const float* inputs = (const float*)d_in[0];   // [1024, 8192]
    const float* adj    = (const float*)d_in[1];   // [8192, 1024]
    const float* prob   = (const float*)d_in[2];   // [8192]
    const float* w      = (const float*)d_in[3];   // [1024, 1024]

    float* out  = (float*)d_out;
    float* mask = (float*)d_out + (size_t)8192 * 8192;

    cudaFuncSetAttribute(gemm2, cudaFuncAttributeMaxDynamicSharedMemorySize, SMEM_TOTAL);

    // inputs^T, split hi/lo
    tkern<<<dim3(256, 32), dim3(32, 8)>>>(inputs, 8192);

    // GEMM1 (fp32 SIMT): T = adj @ (w/17), epilogue splits to gTh/gTl
    sgemm1<<<dim3(1024 / BN, 8192 / BM), 256>>>(adj, w);

    zkern<<<1, 1>>>();

    // GEMM2 (3xTF32, pre-split): pre = T @ inputs, fused epilogue + flagging
    gemm2<<<dim3(8192 / BN, 8192 / BM), 256, SMEM_TOTAL>>>(out, mask, prob);

    // recompute near-threshold elements in exact-order fp32
    fixup<<<1024, 256>>>(out, mask, prob);
}

// round 9
// speedup vs baseline: 1.1900x; 1.1900x over previous
#include <cuda_runtime.h>
#include <cstdint>
#include <cstddef>

// ============================================================================
// interAUGraphConv, GB300 (compute_103 PTX => no tcgen05; mma.sync tf32)
//
//   GEMM1: T[8192,1024]   = adj @ (w/17)     -- fp32 SIMT, sequential-k
//   GEMM2: pre[8192,8192] = T @ inputs       -- 2-term tf32 mma.sync:
//            pre ~= (Th+Tl) @ Bh    (B truncated to tf32; A split exact)
//   out = (0.6<pre<=1 ? pre : 1)/prob[row], mask = pre>0.6
//
// Elements with |pre-0.6| < DELTA are recomputed sequential-k fp32 with EXACT
// operands (A = Th+Tl, B = Bh+Bl, both splits exact) by the fixup pass, so
// every threshold decision matches the fp32 reference pipeline.
// ============================================================================

static const int KDIM = 1024;
static const int BM = 128, BN = 128, BK = 16;
static const int PAD = 20;
static const int TILE_WORDS = 128 * PAD;           // 2560 words per tile
static const int STAGE_WORDS = 3 * TILE_WORDS;     // Ah, Al, Bh
static const int STAGE_B = STAGE_WORDS * 4;        // 30720 bytes
static const int NSTAGE = 4;
static const int SMEM_TOTAL = NSTAGE * STAGE_B;    // 122880

static const unsigned FIX_CAP = 1u << 22;
#define DELTA 3.0e-3f

// ---- device scratch ----
__device__ float gTh[(size_t)8192 * 1024];    // hi(T)
__device__ float gTl[(size_t)8192 * 1024];    // lo(T)   (exact: T = hi+lo)
__device__ float gBh[(size_t)8192 * 1024];    // hi(inputs^T)
__device__ float gBl[(size_t)8192 * 1024];    // lo(inputs^T) (fixup only)
__device__ unsigned gFixCnt;
__device__ unsigned gFix[FIX_CAP];

// ---------------------------------------------------------------------------
__device__ __forceinline__ float tf32r(float x) {
    float r;
    asm("cvt.rna.tf32.f32 %0, %1;" : "=f"(r) : "f"(x));
    return r;
}
__device__ __forceinline__ uint32_t smem_u32(const void* p) {
    uint32_t a;
    asm("{ .reg .u64 t; cvta.to.shared.u64 t, %1; cvt.u32.u64 %0, t; }" : "=r"(a) : "l"(p));
    return a;
}
#define CP_ASYNC16(saddr, gptr) \
    asm volatile("cp.async.cg.shared.global [%0], [%1], 16;" :: "r"(saddr), "l"(gptr))
#define CP_COMMIT() asm volatile("cp.async.commit_group;" ::: "memory")
#define CP_WAIT2()  asm volatile("cp.async.wait_group 2;" ::: "memory")

#define MMA_TF32(d, a, b)                                                   \
    asm volatile(                                                           \
        "mma.sync.aligned.m16n8k8.row.col.f32.tf32.tf32.f32 "               \
        "{%0,%1,%2,%3}, {%4,%5,%6,%7}, {%8,%9}, {%0,%1,%2,%3};"             \
        : "+f"((d)[0]), "+f"((d)[1]), "+f"((d)[2]), "+f"((d)[3])            \
        : "r"((a)[0]), "r"((a)[1]), "r"((a)[2]), "r"((a)[3]),               \
          "r"((b)[0]), "r"((b)[1]))

// ---------------------------------------------------------------------------
// transpose + split: inputs [1024, 8192] -> gBh/gBl [8192, 1024]
// ---------------------------------------------------------------------------
__global__ __launch_bounds__(256) void tkern(const float* __restrict__ in, int N) {
    __shared__ float t[32][33];
    int n0 = blockIdx.x * 32, k0 = blockIdx.y * 32;
    int tx = threadIdx.x, ty = threadIdx.y;    // (32, 8)
    #pragma unroll
    for (int p = 0; p < 4; p++)
        t[ty + p * 8][tx] = in[(size_t)(k0 + ty + p * 8) * N + n0 + tx];
    __syncthreads();
    #pragma unroll
    for (int p = 0; p < 4; p++) {
        float x  = t[tx][ty + p * 8];
        float hi = tf32r(x);
        size_t o = (size_t)(n0 + ty + p * 8) * KDIM + k0 + tx;
        gBh[o] = hi;
        gBl[o] = x - hi;
    }
}

__global__ void zkern() { gFixCnt = 0; }

// ---------------------------------------------------------------------------
// GEMM1: fp32 SIMT sequential-k; epilogue stores split T -> gTh/gTl
// ---------------------------------------------------------------------------
__global__ __launch_bounds__(256, 2)
void sgemm1(const float* __restrict__ A, const float* __restrict__ B)
{
    __shared__ float As[BK][BM + 4];
    __shared__ float Bs[BK][BN];

    const int tid = threadIdx.x;
    const int tx  = tid & 15;
    const int ty  = tid >> 4;
    const int bm  = blockIdx.y * BM;
    const int bn  = blockIdx.x * BN;
    const int K = 1024, N = 1024;
    const float bscale = 1.0f / 17.0f;

    const float* Ab = A + (size_t)bm * K;
    const float* Bb = B + bn;

    float acc[8][8];
    #pragma unroll
    for (int i = 0; i < 8; i++)
        #pragma unroll
        for (int j = 0; j < 8; j++) acc[i][j] = 0.0f;

    for (int k0 = 0; k0 < K; k0 += BK) {
        #pragma unroll
        for (int l = 0; l < 2; l++) {
            int i = tid + l * 256, row = i >> 2, kc = (i & 3) * 4;
            float4 v = *(const float4*)(Ab + (size_t)row * K + (k0 + kc));
            As[kc + 0][row] = v.x; As[kc + 1][row] = v.y;
            As[kc + 2][row] = v.z; As[kc + 3][row] = v.w;
        }
        #pragma unroll
        for (int l = 0; l < 2; l++) {
            int i = tid + l * 256, row = i >> 5, col = (i & 31) * 4;
            float4 v = *(const float4*)(Bb + (size_t)(k0 + row) * N + col);
            v.x *= bscale; v.y *= bscale; v.z *= bscale; v.w *= bscale;
            *(float4*)&Bs[row][col] = v;
        }
        __syncthreads();
        #pragma unroll
        for (int k = 0; k < BK; k++) {
            float regM[8], regN[8];
            *(float4*)&regM[0] = *(const float4*)&As[k][ty * 8];
            *(float4*)&regM[4] = *(const float4*)&As[k][ty * 8 + 4];
            *(float4*)&regN[0] = *(const float4*)&Bs[k][tx * 8];
            *(float4*)&regN[4] = *(const float4*)&Bs[k][tx * 8 + 4];
            #pragma unroll
            for (int i = 0; i < 8; i++)
                #pragma unroll
                for (int j = 0; j < 8; j++)
                    acc[i][j] += regM[i] * regN[j];
        }
        __syncthreads();
    }
    #pragma unroll
    for (int i = 0; i < 8; i++) {
        int r = bm + ty * 8 + i;
        #pragma unroll
        for (int jj = 0; jj < 8; jj += 4) {
            float4 hv, lv;
            #pragma unroll
            for (int q = 0; q < 4; q++) {
                float x  = acc[i][jj + q];
                float hi = tf32r(x);
                ((float*)&hv)[q] = hi;
                ((float*)&lv)[q] = x - hi;
            }
            size_t off = (size_t)r * N + (bn + tx * 8 + jj);
            *(float4*)(gTh + off) = hv;
            *(float4*)(gTl + off) = lv;
        }
    }
}

// ---------------------------------------------------------------------------
// GEMM2: 2-term tf32 mma.sync (Ah*Bh + Al*Bh) + flagging epilogue
// ---------------------------------------------------------------------------
__device__ __forceinline__ void fill_stage2(uint32_t sm, int buf, int kc,
                                            int bm, int bn, int tid) {
    uint32_t base = sm + buf * STAGE_B;
    #pragma unroll
    for (int t = 0; t < 2; t++) {
        int idx = tid + t * 256;
        int row = idx >> 2, q = idx & 3;
        uint32_t so = (uint32_t)(row * PAD + q * 4) * 4;
        size_t ga = (size_t)(bm + row) * KDIM + kc * BK + q * 4;
        size_t gb = (size_t)(bn + row) * KDIM + kc * BK + q * 4;
        CP_ASYNC16(base + so,                    gTh + ga);
        CP_ASYNC16(base + TILE_WORDS * 4 + so,   gTl + ga);
        CP_ASYNC16(base + TILE_WORDS * 8 + so,   gBh + gb);
    }
}

__global__ __launch_bounds__(256, 1)
void gemm2(float* __restrict__ outp, float* __restrict__ maskp,
           const float* __restrict__ prob)
{
    extern __shared__ float smem[];
    uint32_t sm = smem_u32(smem);

    const int tid  = threadIdx.x;
    const int w    = tid >> 5;
    const int lane = tid & 31;
    const int g    = lane >> 2;
    const int tg   = lane & 3;
    const int warpM = (w & 1) * 64;
    const int warpN = (w >> 1) * 32;
    const int bm = blockIdx.y * BM;
    const int bn = blockIdx.x * BN;

    float d[4][4][4];
    #pragma unroll
    for (int i = 0; i < 4; i++)
        #pragma unroll
        for (int j = 0; j < 4; j++)
            #pragma unroll
            for (int c = 0; c < 4; c++) d[i][j][c] = 0.0f;

    fill_stage2(sm, 0, 0, bm, bn, tid); CP_COMMIT();
    fill_stage2(sm, 1, 1, bm, bn, tid); CP_COMMIT();
    fill_stage2(sm, 2, 2, bm, bn, tid); CP_COMMIT();

    const int NCH = KDIM / BK;   // 64
    for (int i = 0; i < NCH; i++) {
        CP_WAIT2();               // stage i resident (<=2 younger pending)
        __syncthreads();
        int j = i + 3;
        if (j < NCH) fill_stage2(sm, j & 3, j, bm, bn, tid);
        CP_COMMIT();

        const float* Ash = smem + (i & 3) * STAGE_WORDS;
        const float* Asl = Ash + TILE_WORDS;
        const float* Bsh = Ash + 2 * TILE_WORDS;

        #pragma unroll
        for (int ks = 0; ks < 2; ks++) {
            uint32_t ah[4][4], al[4][4], bh[4][2];
            #pragma unroll
            for (int mt = 0; mt < 4; mt++) {
                int m = warpM + mt * 16 + g;
                int o0 = m * PAD + ks * 8 + tg;
                int o1 = (m + 8) * PAD + ks * 8 + tg;
                ah[mt][0] = __float_as_uint(Ash[o0]);
                ah[mt][1] = __float_as_uint(Ash[o1]);
                ah[mt][2] = __float_as_uint(Ash[o0 + 4]);
                ah[mt][3] = __float_as_uint(Ash[o1 + 4]);
                al[mt][0] = __float_as_uint(Asl[o0]);
                al[mt][1] = __float_as_uint(Asl[o1]);
                al[mt][2] = __float_as_uint(Asl[o0 + 4]);
                al[mt][3] = __float_as_uint(Asl[o1 + 4]);
            }
            #pragma unroll
            for (int nt = 0; nt < 4; nt++) {
                int n = warpN + nt * 8 + g;
                int o = n * PAD + ks * 8 + tg;
                bh[nt][0] = __float_as_uint(Bsh[o]);
                bh[nt][1] = __float_as_uint(Bsh[o + 4]);
            }
            #pragma unroll
            for (int mt = 0; mt < 4; mt++)
                #pragma unroll
                for (int nt = 0; nt < 4; nt++) MMA_TF32(d[mt][nt], ah[mt], bh[nt]);
            #pragma unroll
            for (int mt = 0; mt < 4; mt++)
                #pragma unroll
                for (int nt = 0; nt < 4; nt++) MMA_TF32(d[mt][nt], al[mt], bh[nt]);
        }
        __syncthreads();
    }

    // ---- epilogue: activation + mask + near-threshold flagging ----
    #pragma unroll
    for (int mt = 0; mt < 4; mt++) {
        int r0 = bm + warpM + mt * 16 + g;
        int r1 = r0 + 8;
        float rp0 = 1.0f / prob[r0];
        float rp1 = 1.0f / prob[r1];
        #pragma unroll
        for (int nt = 0; nt < 4; nt++) {
            int c = bn + warpN + nt * 8 + tg * 2;
            float2 o0, o1, m0, m1;
            #pragma unroll
            for (int q = 0; q < 4; q++) {
                float pre = d[mt][nt][q];
                int   rr  = (q < 2) ? r0 : r1;
                int   cc  = c + (q & 1);
                bool  gt  = pre > 0.6f;
                float act = (gt && pre <= 1.0f) ? pre : 1.0f;
                float rv  = act * ((q < 2) ? rp0 : rp1);
                float mv  = gt ? 1.0f : 0.0f;
                if (q == 0) { o0.x = rv; m0.x = mv; }
                else if (q == 1) { o0.y = rv; m0.y = mv; }
                else if (q == 2) { o1.x = rv; m1.x = mv; }
                else { o1.y = rv; m1.y = mv; }
                if (fabsf(pre - 0.6f) < DELTA) {
                    unsigned idx = atomicAdd(&gFixCnt, 1u);
                    if (idx < FIX_CAP)
                        gFix[idx] = ((unsigned)rr << 13) | (unsigned)cc;
                }
            }
            *(float2*)(outp  + (size_t)r0 * 8192 + c) = o0;
            *(float2*)(outp  + (size_t)r1 * 8192 + c) = o1;
            *(float2*)(maskp + (size_t)r0 * 8192 + c) = m0;
            *(float2*)(maskp + (size_t)r1 * 8192 + c) = m1;
        }
    }
}

// ---------------------------------------------------------------------------
// fixup: recompute flagged elements, sequential-k fp32 (operands exact hi+lo)
// ---------------------------------------------------------------------------
__global__ __launch_bounds__(256)
void fixup(float* __restrict__ outp, float* __restrict__ maskp,
           const float* __restrict__ prob)
{
    unsigned cnt = gFixCnt;
    if (cnt > FIX_CAP) cnt = FIX_CAP;
    unsigned stride = gridDim.x * blockDim.x;
    for (unsigned i = blockIdx.x * blockDim.x + threadIdx.x; i < cnt; i += stride) {
        unsigned e = gFix[i];
        int m = e >> 13;
        int n = e & 8191;
        const float4* ath = (const float4*)(gTh + (size_t)m * KDIM);
        const float4* atl = (const float4*)(gTl + (size_t)m * KDIM);
        const float4* bth = (const float4*)(gBh + (size_t)n * KDIM);
        const float4* btl = (const float4*)(gBl + (size_t)n * KDIM);
        float s = 0.0f;
        #pragma unroll 4
        for (int k = 0; k < KDIM / 4; k++) {
            float4 ah = ath[k], al = atl[k], bh = bth[k], bl = btl[k];
            s = fmaf(ah.x + al.x, bh.x + bl.x, s);
            s = fmaf(ah.y + al.y, bh.y + bl.y, s);
            s = fmaf(ah.z + al.z, bh.z + bl.z, s);
            s = fmaf(ah.w + al.w, bh.w + bl.w, s);
        }
        bool  gt  = s > 0.6f;
        float act = (gt && s <= 1.0f) ? s : 1.0f;
        size_t off = (size_t)m * 8192 + n;
        outp[off]  = act * (1.0f / prob[m]);
        maskp[off] = gt ? 1.0f : 0.0f;
    }
}

// ---------------------------------------------------------------------------
extern "C" void kernel_launch(void* const* d_in, const int* in_sizes, int n_in,
                              void* d_out, int out_size)
{
    const float* inputs = (const float*)d_in[0];   // [1024, 8192]
    const float* adj    = (const float*)d_in[1];   // [8192, 1024]
    const float* prob   = (const float*)d_in[2];   // [8192]
    const float* w      = (const float*)d_in[3];   // [1024, 1024]

    float* out  = (float*)d_out;
    float* mask = (float*)d_out + (size_t)8192 * 8192;

    cudaFuncSetAttribute(gemm2, cudaFuncAttributeMaxDynamicSharedMemorySize, SMEM_TOTAL);

    // inputs^T, split hi/lo
    tkern<<<dim3(256, 32), dim3(32, 8)>>>(inputs, 8192);

    // GEMM1 (fp32 SIMT): T = adj @ (w/17), epilogue splits to gTh/gTl
    sgemm1<<<dim3(1024 / BN, 8192 / BM), 256>>>(adj, w);

    zkern<<<1, 1>>>();

    // GEMM2 (2-term tf32): pre ~= T @ tf32(inputs), fused epilogue + flagging
    gemm2<<<dim3(8192 / BN, 8192 / BM), 256, SMEM_TOTAL>>>(out, mask, prob);

    // recompute near-threshold elements in exact-order fp32
    fixup<<<1024, 256>>>(out, mask, prob);
}

// round 13
// speedup vs baseline: 1.3136x; 1.1039x over previous
#include <cuda_runtime.h>
#include <cstdint>
#include <cstddef>

// ============================================================================
// interAUGraphConv, GB300 (compute_103 PTX => no tcgen05; mma.sync tf32)
//
//   GEMM1: T[8192,1024]   = adj @ (w/17)     -- fp32 SIMT, sequential-k
//   GEMM2: pre[8192,8192] = T @ inputs       -- 2-term tf32 mma.sync:
//            pre ~= (Th+Tl) @ Bh    (B truncated to tf32; A split exact)
//   out = (0.6<pre<=1 ? pre : 1)/prob[row], mask = pre>0.6
//
// Elements with |pre-0.6| < DELTA are recomputed sequential-k fp32 with EXACT
// operands (A = Th+Tl, B = Bh+Bl, both splits exact) by the fixup pass, so
// every threshold decision matches the fp32 pipeline.
//
// Round 10: gemm2 at 2 CTAs/SM (3 stages, 90KB smem, <=128 regs) to hide MMA
// latency and barrier cost that capped tensor% at 47.5 with 1 CTA/SM.
// ============================================================================

static const int KDIM = 1024;
static const int BM = 128, BN = 128, BK = 16;
static const int PAD = 20;
static const int TILE_WORDS = 128 * PAD;           // 2560 words per tile
static const int STAGE_WORDS = 3 * TILE_WORDS;     // Ah, Al, Bh
static const int STAGE_B = STAGE_WORDS * 4;        // 30720 bytes
static const int NSTAGE = 3;
static const int SMEM_TOTAL = NSTAGE * STAGE_B;    // 92160 (2 CTAs/SM fit)

static const unsigned FIX_CAP = 1u << 22;
#define DELTA 3.0e-3f

// ---- device scratch ----
__device__ float gTh[(size_t)8192 * 1024];    // hi(T)
__device__ float gTl[(size_t)8192 * 1024];    // lo(T)   (exact: T = hi+lo)
__device__ float gBh[(size_t)8192 * 1024];    // hi(inputs^T)
__device__ float gBl[(size_t)8192 * 1024];    // lo(inputs^T) (fixup only)
__device__ unsigned gFixCnt;
__device__ unsigned gFix[FIX_CAP];

// ---------------------------------------------------------------------------
__device__ __forceinline__ float tf32r(float x) {
    float r;
    asm("cvt.rna.tf32.f32 %0, %1;" : "=f"(r) : "f"(x));
    return r;
}
__device__ __forceinline__ uint32_t smem_u32(const void* p) {
    uint32_t a;
    asm("{ .reg .u64 t; cvta.to.shared.u64 t, %1; cvt.u32.u64 %0, t; }" : "=r"(a) : "l"(p));
    return a;
}
#define CP_ASYNC16(saddr, gptr) \
    asm volatile("cp.async.cg.shared.global [%0], [%1], 16;" :: "r"(saddr), "l"(gptr))
#define CP_COMMIT() asm volatile("cp.async.commit_group;" ::: "memory")
#define CP_WAIT1()  asm volatile("cp.async.wait_group 1;" ::: "memory")

#define MMA_TF32(d, a, b)                                                   \
    asm volatile(                                                           \
        "mma.sync.aligned.m16n8k8.row.col.f32.tf32.tf32.f32 "               \
        "{%0,%1,%2,%3}, {%4,%5,%6,%7}, {%8,%9}, {%0,%1,%2,%3};"             \
        : "+f"((d)[0]), "+f"((d)[1]), "+f"((d)[2]), "+f"((d)[3])            \
        : "r"((a)[0]), "r"((a)[1]), "r"((a)[2]), "r"((a)[3]),               \
          "r"((b)[0]), "r"((b)[1]))

// ---------------------------------------------------------------------------
// transpose + split: inputs [1024, 8192] -> gBh/gBl [8192, 1024]
// (also clears the fixup counter: runs before gemm2)
// ---------------------------------------------------------------------------
__global__ __launch_bounds__(256) void tkern(const float* __restrict__ in, int N) {
    __shared__ float t[32][33];
    if (blockIdx.x == 0 && blockIdx.y == 0 && threadIdx.x == 0 && threadIdx.y == 0)
        gFixCnt = 0;
    int n0 = blockIdx.x * 32, k0 = blockIdx.y * 32;
    int tx = threadIdx.x, ty = threadIdx.y;    // (32, 8)
    #pragma unroll
    for (int p = 0; p < 4; p++)
        t[ty + p * 8][tx] = in[(size_t)(k0 + ty + p * 8) * N + n0 + tx];
    __syncthreads();
    #pragma unroll
    for (int p = 0; p < 4; p++) {
        float x  = t[tx][ty + p * 8];
        float hi = tf32r(x);
        size_t o = (size_t)(n0 + ty + p * 8) * KDIM + k0 + tx;
        gBh[o] = hi;
        gBl[o] = x - hi;
    }
}

// ---------------------------------------------------------------------------
// GEMM1: fp32 SIMT sequential-k; epilogue stores split T -> gTh/gTl
// ---------------------------------------------------------------------------
__global__ __launch_bounds__(256, 2)
void sgemm1(const float* __restrict__ A, const float* __restrict__ B)
{
    __shared__ float As[BK][BM + 4];
    __shared__ float Bs[BK][BN];

    const int tid = threadIdx.x;
    const int tx  = tid & 15;
    const int ty  = tid >> 4;
    const int bm  = blockIdx.y * BM;
    const int bn  = blockIdx.x * BN;
    const int K = 1024, N = 1024;
    const float bscale = 1.0f / 17.0f;

    const float* Ab = A + (size_t)bm * K;
    const float* Bb = B + bn;

    float acc[8][8];
    #pragma unroll
    for (int i = 0; i < 8; i++)
        #pragma unroll
        for (int j = 0; j < 8; j++) acc[i][j] = 0.0f;

    for (int k0 = 0; k0 < K; k0 += BK) {
        #pragma unroll
        for (int l = 0; l < 2; l++) {
            int i = tid + l * 256, row = i >> 2, kc = (i & 3) * 4;
            float4 v = *(const float4*)(Ab + (size_t)row * K + (k0 + kc));
            As[kc + 0][row] = v.x; As[kc + 1][row] = v.y;
            As[kc + 2][row] = v.z; As[kc + 3][row] = v.w;
        }
        #pragma unroll
        for (int l = 0; l < 2; l++) {
            int i = tid + l * 256, row = i >> 5, col = (i & 31) * 4;
            float4 v = *(const float4*)(Bb + (size_t)(k0 + row) * N + col);
            v.x *= bscale; v.y *= bscale; v.z *= bscale; v.w *= bscale;
            *(float4*)&Bs[row][col] = v;
        }
        __syncthreads();
        #pragma unroll
        for (int k = 0; k < BK; k++) {
            float regM[8], regN[8];
            *(float4*)&regM[0] = *(const float4*)&As[k][ty * 8];
            *(float4*)&regM[4] = *(const float4*)&As[k][ty * 8 + 4];
            *(float4*)&regN[0] = *(const float4*)&Bs[k][tx * 8];
            *(float4*)&regN[4] = *(const float4*)&Bs[k][tx * 8 + 4];
            #pragma unroll
            for (int i = 0; i < 8; i++)
                #pragma unroll
                for (int j = 0; j < 8; j++)
                    acc[i][j] += regM[i] * regN[j];
        }
        __syncthreads();
    }
    #pragma unroll
    for (int i = 0; i < 8; i++) {
        int r = bm + ty * 8 + i;
        #pragma unroll
        for (int jj = 0; jj < 8; jj += 4) {
            float4 hv, lv;
            #pragma unroll
            for (int q = 0; q < 4; q++) {
                float x  = acc[i][jj + q];
                float hi = tf32r(x);
                ((float*)&hv)[q] = hi;
                ((float*)&lv)[q] = x - hi;
            }
            size_t off = (size_t)r * N + (bn + tx * 8 + jj);
            *(float4*)(gTh + off) = hv;
            *(float4*)(gTl + off) = lv;
        }
    }
}

// ---------------------------------------------------------------------------
// GEMM2: 2-term tf32 mma.sync (Ah*Bh + Al*Bh) + flagging epilogue
// ---------------------------------------------------------------------------
__device__ __forceinline__ void fill_stage2(uint32_t sm, int buf, int kc,
                                            int bm, int bn, int tid) {
    uint32_t base = sm + buf * STAGE_B;
    #pragma unroll
    for (int t = 0; t < 2; t++) {
        int idx = tid + t * 256;
        int row = idx >> 2, q = idx & 3;
        uint32_t so = (uint32_t)(row * PAD + q * 4) * 4;
        size_t ga = (size_t)(bm + row) * KDIM + kc * BK + q * 4;
        size_t gb = (size_t)(bn + row) * KDIM + kc * BK + q * 4;
        CP_ASYNC16(base + so,                    gTh + ga);
        CP_ASYNC16(base + TILE_WORDS * 4 + so,   gTl + ga);
        CP_ASYNC16(base + TILE_WORDS * 8 + so,   gBh + gb);
    }
}

__global__ __launch_bounds__(256, 2)
void gemm2(float* __restrict__ outp, float* __restrict__ maskp,
           const float* __restrict__ prob)
{
    extern __shared__ float smem[];
    uint32_t sm = smem_u32(smem);

    const int tid  = threadIdx.x;
    const int w    = tid >> 5;
    const int lane = tid & 31;
    const int g    = lane >> 2;
    const int tg   = lane & 3;
    const int warpM = (w & 1) * 64;
    const int warpN = (w >> 1) * 32;
    const int bm = blockIdx.y * BM;
    const int bn = blockIdx.x * BN;

    float d[4][4][4];
    #pragma unroll
    for (int i = 0; i < 4; i++)
        #pragma unroll
        for (int j = 0; j < 4; j++)
            #pragma unroll
            for (int c = 0; c < 4; c++) d[i][j][c] = 0.0f;

    fill_stage2(sm, 0, 0, bm, bn, tid); CP_COMMIT();
    fill_stage2(sm, 1, 1, bm, bn, tid); CP_COMMIT();

    const int NCH = KDIM / BK;   // 64
    int buf = 0;
    for (int i = 0; i < NCH; i++) {
        CP_WAIT1();               // stage i resident (<=1 younger pending)
        __syncthreads();
        int j = i + 2;
        int pbuf = buf + 2; if (pbuf >= 3) pbuf -= 3;
        if (j < NCH) fill_stage2(sm, pbuf, j, bm, bn, tid);
        CP_COMMIT();

        const float* Ash = smem + buf * STAGE_WORDS;
        const float* Asl = Ash + TILE_WORDS;
        const float* Bsh = Ash + 2 * TILE_WORDS;

        #pragma unroll
        for (int ks = 0; ks < 2; ks++) {
            uint32_t ah[4][4], al[4][4], bh[4][2];
            #pragma unroll
            for (int mt = 0; mt < 4; mt++) {
                int m = warpM + mt * 16 + g;
                int o0 = m * PAD + ks * 8 + tg;
                int o1 = (m + 8) * PAD + ks * 8 + tg;
                ah[mt][0] = __float_as_uint(Ash[o0]);
                ah[mt][1] = __float_as_uint(Ash[o1]);
                ah[mt][2] = __float_as_uint(Ash[o0 + 4]);
                ah[mt][3] = __float_as_uint(Ash[o1 + 4]);
                al[mt][0] = __float_as_uint(Asl[o0]);
                al[mt][1] = __float_as_uint(Asl[o1]);
                al[mt][2] = __float_as_uint(Asl[o0 + 4]);
                al[mt][3] = __float_as_uint(Asl[o1 + 4]);
            }
            #pragma unroll
            for (int nt = 0; nt < 4; nt++) {
                int n = warpN + nt * 8 + g;
                int o = n * PAD + ks * 8 + tg;
                bh[nt][0] = __float_as_uint(Bsh[o]);
                bh[nt][1] = __float_as_uint(Bsh[o + 4]);
            }
            #pragma unroll
            for (int mt = 0; mt < 4; mt++)
                #pragma unroll
                for (int nt = 0; nt < 4; nt++) MMA_TF32(d[mt][nt], ah[mt], bh[nt]);
            #pragma unroll
            for (int mt = 0; mt < 4; mt++)
                #pragma unroll
                for (int nt = 0; nt < 4; nt++) MMA_TF32(d[mt][nt], al[mt], bh[nt]);
        }
        __syncthreads();
        if (++buf == 3) buf = 0;
    }

    // ---- epilogue: activation + mask + near-threshold flagging ----
    #pragma unroll
    for (int mt = 0; mt < 4; mt++) {
        int r0 = bm + warpM + mt * 16 + g;
        int r1 = r0 + 8;
        float rp0 = 1.0f / prob[r0];
        float rp1 = 1.0f / prob[r1];
        #pragma unroll
        for (int nt = 0; nt < 4; nt++) {
            int c = bn + warpN + nt * 8 + tg * 2;
            float2 o0, o1, m0, m1;
            #pragma unroll
            for (int q = 0; q < 4; q++) {
                float pre = d[mt][nt][q];
                int   rr  = (q < 2) ? r0 : r1;
                int   cc  = c + (q & 1);
                bool  gt  = pre > 0.6f;
                float act = (gt && pre <= 1.0f) ? pre : 1.0f;
                float rv  = act * ((q < 2) ? rp0 : rp1);
                float mv  = gt ? 1.0f : 0.0f;
                if (q == 0) { o0.x = rv; m0.x = mv; }
                else if (q == 1) { o0.y = rv; m0.y = mv; }
                else if (q == 2) { o1.x = rv; m1.x = mv; }
                else { o1.y = rv; m1.y = mv; }
                if (fabsf(pre - 0.6f) < DELTA) {
                    unsigned idx = atomicAdd(&gFixCnt, 1u);
                    if (idx < FIX_CAP)
                        gFix[idx] = ((unsigned)rr << 13) | (unsigned)cc;
                }
            }
            *(float2*)(outp  + (size_t)r0 * 8192 + c) = o0;
            *(float2*)(outp  + (size_t)r1 * 8192 + c) = o1;
            *(float2*)(maskp + (size_t)r0 * 8192 + c) = m0;
            *(float2*)(maskp + (size_t)r1 * 8192 + c) = m1;
        }
    }
}

// ---------------------------------------------------------------------------
// fixup: recompute flagged elements, sequential-k fp32 (operands exact hi+lo)
// ---------------------------------------------------------------------------
__global__ __launch_bounds__(256)
void fixup(float* __restrict__ outp, float* __restrict__ maskp,
           const float* __restrict__ prob)
{
    unsigned cnt = gFixCnt;
    if (cnt > FIX_CAP) cnt = FIX_CAP;
    unsigned stride = gridDim.x * blockDim.x;
    for (unsigned i = blockIdx.x * blockDim.x + threadIdx.x; i < cnt; i += stride) {
        unsigned e = gFix[i];
        int m = e >> 13;
        int n = e & 8191;
        const float4* ath = (const float4*)(gTh + (size_t)m * KDIM);
        const float4* atl = (const float4*)(gTl + (size_t)m * KDIM);
        const float4* bth = (const float4*)(gBh + (size_t)n * KDIM);
        const float4* btl = (const float4*)(gBl + (size_t)n * KDIM);
        float s = 0.0f;
        #pragma unroll 4
        for (int k = 0; k < KDIM / 4; k++) {
            float4 ah = ath[k], al = atl[k], bh = bth[k], bl = btl[k];
            s = fmaf(ah.x + al.x, bh.x + bl.x, s);
            s = fmaf(ah.y + al.y, bh.y + bl.y, s);
            s = fmaf(ah.z + al.z, bh.z + bl.z, s);
            s = fmaf(ah.w + al.w, bh.w + bl.w, s);
        }
        bool  gt  = s > 0.6f;
        float act = (gt && s <= 1.0f) ? s : 1.0f;
        size_t off = (size_t)m * 8192 + n;
        outp[off]  = act * (1.0f / prob[m]);
        maskp[off] = gt ? 1.0f : 0.0f;
    }
}

// ---------------------------------------------------------------------------
extern "C" void kernel_launch(void* const* d_in, const int* in_sizes, int n_in,
                              void* d_out, int out_size)
{
    const float* inputs = (const float*)d_in[0];   // [1024, 8192]
    const float* adj    = (const float*)d_in[1];   // [8192, 1024]
    const float* prob   = (const float*)d_in[2];   // [8192]
    const float* w      = (const float*)d_in[3];   // [1024, 1024]

    float* out  = (float*)d_out;
    float* mask = (float*)d_out + (size_t)8192 * 8192;

    cudaFuncSetAttribute(gemm2, cudaFuncAttributeMaxDynamicSharedMemorySize, SMEM_TOTAL);

    // inputs^T, split hi/lo (also zeroes fixup counter)
    tkern<<<dim3(256, 32), dim3(32, 8)>>>(inputs, 8192);

    // GEMM1 (fp32 SIMT): T = adj @ (w/17), epilogue splits to gTh/gTl
    sgemm1<<<dim3(1024 / BN, 8192 / BM), 256>>>(adj, w);

    // GEMM2 (2-term tf32): pre ~= T @ tf32(inputs), fused epilogue + flagging
    gemm2<<<dim3(8192 / BN, 8192 / BM), 256, SMEM_TOTAL>>>(out, mask, prob);

    // recompute near-threshold elements in exact-order fp32
    fixup<<<1024, 256>>>(out, mask, prob);
}

// round 15
// speedup vs baseline: 1.5582x; 1.1862x over previous
#include <cuda_runtime.h>
#include <cstdint>
#include <cstddef>

// ============================================================================
// interAUGraphConv, GB300 (compute_103 PTX => no tcgen05; mma.sync tf32)
//
//   GEMM1: T[8192,1024]   = adj @ (w/17)     -- fp32 SIMT, sequential-k
//   GEMM2: pre[8192,8192] = T @ inputs       -- 2-term tf32 mma.sync:
//            pre ~= (Th+Tl) @ Bh    (B truncated to tf32; A split exact)
//   out = (0.6<pre<=1 ? pre : 1)/prob[row], mask = pre>0.6
//
// Elements with |pre-0.6| < DELTA are recomputed in fp32 with EXACT operands
// (A = Th+Tl, B = Bh+Bl) by a warp-per-element fixup pass (round 14: was
// thread-per-element with a 1024-deep serial fma chain -> 650us latency-bound).
// ============================================================================

static const int KDIM = 1024;
static const int BM = 128, BN = 128, BK = 16;
static const int PAD = 20;
static const int TILE_WORDS = 128 * PAD;           // 2560 words per tile
static const int STAGE_WORDS = 3 * TILE_WORDS;     // Ah, Al, Bh
static const int STAGE_B = STAGE_WORDS * 4;        // 30720 bytes
static const int NSTAGE = 3;
static const int SMEM_TOTAL = NSTAGE * STAGE_B;    // 92160 (2 CTAs/SM fit)

static const unsigned FIX_CAP = 1u << 22;
#define DELTA 3.0e-3f

// ---- device scratch ----
__device__ float gTh[(size_t)8192 * 1024];    // hi(T)
__device__ float gTl[(size_t)8192 * 1024];    // lo(T)   (exact: T = hi+lo)
__device__ float gBh[(size_t)8192 * 1024];    // hi(inputs^T)
__device__ float gBl[(size_t)8192 * 1024];    // lo(inputs^T) (fixup only)
__device__ unsigned gFixCnt;
__device__ unsigned gFix[FIX_CAP];

// ---------------------------------------------------------------------------
__device__ __forceinline__ float tf32r(float x) {
    float r;
    asm("cvt.rna.tf32.f32 %0, %1;" : "=f"(r) : "f"(x));
    return r;
}
__device__ __forceinline__ uint32_t smem_u32(const void* p) {
    uint32_t a;
    asm("{ .reg .u64 t; cvta.to.shared.u64 t, %1; cvt.u32.u64 %0, t; }" : "=r"(a) : "l"(p));
    return a;
}
#define CP_ASYNC16(saddr, gptr) \
    asm volatile("cp.async.cg.shared.global [%0], [%1], 16;" :: "r"(saddr), "l"(gptr))
#define CP_COMMIT() asm volatile("cp.async.commit_group;" ::: "memory")
#define CP_WAIT1()  asm volatile("cp.async.wait_group 1;" ::: "memory")

#define MMA_TF32(d, a, b)                                                   \
    asm volatile(                                                           \
        "mma.sync.aligned.m16n8k8.row.col.f32.tf32.tf32.f32 "               \
        "{%0,%1,%2,%3}, {%4,%5,%6,%7}, {%8,%9}, {%0,%1,%2,%3};"             \
        : "+f"((d)[0]), "+f"((d)[1]), "+f"((d)[2]), "+f"((d)[3])            \
        : "r"((a)[0]), "r"((a)[1]), "r"((a)[2]), "r"((a)[3]),               \
          "r"((b)[0]), "r"((b)[1]))

// ---------------------------------------------------------------------------
// transpose + split: inputs [1024, 8192] -> gBh/gBl [8192, 1024]
// (also clears the fixup counter: runs before gemm2)
// ---------------------------------------------------------------------------
__global__ __launch_bounds__(256) void tkern(const float* __restrict__ in, int N) {
    __shared__ float t[32][33];
    if (blockIdx.x == 0 && blockIdx.y == 0 && threadIdx.x == 0 && threadIdx.y == 0)
        gFixCnt = 0;
    int n0 = blockIdx.x * 32, k0 = blockIdx.y * 32;
    int tx = threadIdx.x, ty = threadIdx.y;    // (32, 8)
    #pragma unroll
    for (int p = 0; p < 4; p++)
        t[ty + p * 8][tx] = in[(size_t)(k0 + ty + p * 8) * N + n0 + tx];
    __syncthreads();
    #pragma unroll
    for (int p = 0; p < 4; p++) {
        float x  = t[tx][ty + p * 8];
        float hi = tf32r(x);
        size_t o = (size_t)(n0 + ty + p * 8) * KDIM + k0 + tx;
        gBh[o] = hi;
        gBl[o] = x - hi;
    }
}

// ---------------------------------------------------------------------------
// GEMM1: fp32 SIMT sequential-k; epilogue stores split T -> gTh/gTl
// ---------------------------------------------------------------------------
__global__ __launch_bounds__(256, 2)
void sgemm1(const float* __restrict__ A, const float* __restrict__ B)
{
    __shared__ float As[BK][BM + 4];
    __shared__ float Bs[BK][BN];

    const int tid = threadIdx.x;
    const int tx  = tid & 15;
    const int ty  = tid >> 4;
    const int bm  = blockIdx.y * BM;
    const int bn  = blockIdx.x * BN;
    const int K = 1024, N = 1024;
    const float bscale = 1.0f / 17.0f;

    const float* Ab = A + (size_t)bm * K;
    const float* Bb = B + bn;

    float acc[8][8];
    #pragma unroll
    for (int i = 0; i < 8; i++)
        #pragma unroll
        for (int j = 0; j < 8; j++) acc[i][j] = 0.0f;

    for (int k0 = 0; k0 < K; k0 += BK) {
        #pragma unroll
        for (int l = 0; l < 2; l++) {
            int i = tid + l * 256, row = i >> 2, kc = (i & 3) * 4;
            float4 v = *(const float4*)(Ab + (size_t)row * K + (k0 + kc));
            As[kc + 0][row] = v.x; As[kc + 1][row] = v.y;
            As[kc + 2][row] = v.z; As[kc + 3][row] = v.w;
        }
        #pragma unroll
        for (int l = 0; l < 2; l++) {
            int i = tid + l * 256, row = i >> 5, col = (i & 31) * 4;
            float4 v = *(const float4*)(Bb + (size_t)(k0 + row) * N + col);
            v.x *= bscale; v.y *= bscale; v.z *= bscale; v.w *= bscale;
            *(float4*)&Bs[row][col] = v;
        }
        __syncthreads();
        #pragma unroll
        for (int k = 0; k < BK; k++) {
            float regM[8], regN[8];
            *(float4*)&regM[0] = *(const float4*)&As[k][ty * 8];
            *(float4*)&regM[4] = *(const float4*)&As[k][ty * 8 + 4];
            *(float4*)&regN[0] = *(const float4*)&Bs[k][tx * 8];
            *(float4*)&regN[4] = *(const float4*)&Bs[k][tx * 8 + 4];
            #pragma unroll
            for (int i = 0; i < 8; i++)
                #pragma unroll
                for (int j = 0; j < 8; j++)
                    acc[i][j] += regM[i] * regN[j];
        }
        __syncthreads();
    }
    #pragma unroll
    for (int i = 0; i < 8; i++) {
        int r = bm + ty * 8 + i;
        #pragma unroll
        for (int jj = 0; jj < 8; jj += 4) {
            float4 hv, lv;
            #pragma unroll
            for (int q = 0; q < 4; q++) {
                float x  = acc[i][jj + q];
                float hi = tf32r(x);
                ((float*)&hv)[q] = hi;
                ((float*)&lv)[q] = x - hi;
            }
            size_t off = (size_t)r * N + (bn + tx * 8 + jj);
            *(float4*)(gTh + off) = hv;
            *(float4*)(gTl + off) = lv;
        }
    }
}

// ---------------------------------------------------------------------------
// GEMM2: 2-term tf32 mma.sync (Ah*Bh + Al*Bh) + flagging epilogue
// ---------------------------------------------------------------------------
__device__ __forceinline__ void fill_stage2(uint32_t sm, int buf, int kc,
                                            int bm, int bn, int tid) {
    uint32_t base = sm + buf * STAGE_B;
    #pragma unroll
    for (int t = 0; t < 2; t++) {
        int idx = tid + t * 256;
        int row = idx >> 2, q = idx & 3;
        uint32_t so = (uint32_t)(row * PAD + q * 4) * 4;
        size_t ga = (size_t)(bm + row) * KDIM + kc * BK + q * 4;
        size_t gb = (size_t)(bn + row) * KDIM + kc * BK + q * 4;
        CP_ASYNC16(base + so,                    gTh + ga);
        CP_ASYNC16(base + TILE_WORDS * 4 + so,   gTl + ga);
        CP_ASYNC16(base + TILE_WORDS * 8 + so,   gBh + gb);
    }
}

__global__ __launch_bounds__(256, 2)
void gemm2(float* __restrict__ outp, float* __restrict__ maskp,
           const float* __restrict__ prob)
{
    extern __shared__ float smem[];
    uint32_t sm = smem_u32(smem);

    const int tid  = threadIdx.x;
    const int w    = tid >> 5;
    const int lane = tid & 31;
    const int g    = lane >> 2;
    const int tg   = lane & 3;
    const int warpM = (w & 1) * 64;
    const int warpN = (w >> 1) * 32;
    const int bm = blockIdx.y * BM;
    const int bn = blockIdx.x * BN;

    float d[4][4][4];
    #pragma unroll
    for (int i = 0; i < 4; i++)
        #pragma unroll
        for (int j = 0; j < 4; j++)
            #pragma unroll
            for (int c = 0; c < 4; c++) d[i][j][c] = 0.0f;

    fill_stage2(sm, 0, 0, bm, bn, tid); CP_COMMIT();
    fill_stage2(sm, 1, 1, bm, bn, tid); CP_COMMIT();

    const int NCH = KDIM / BK;   // 64
    int buf = 0;
    for (int i = 0; i < NCH; i++) {
        CP_WAIT1();               // stage i resident (<=1 younger pending)
        __syncthreads();
        int j = i + 2;
        int pbuf = buf + 2; if (pbuf >= 3) pbuf -= 3;
        if (j < NCH) fill_stage2(sm, pbuf, j, bm, bn, tid);
        CP_COMMIT();

        const float* Ash = smem + buf * STAGE_WORDS;
        const float* Asl = Ash + TILE_WORDS;
        const float* Bsh = Ash + 2 * TILE_WORDS;

        #pragma unroll
        for (int ks = 0; ks < 2; ks++) {
            uint32_t ah[4][4], al[4][4], bh[4][2];
            #pragma unroll
            for (int mt = 0; mt < 4; mt++) {
                int m = warpM + mt * 16 + g;
                int o0 = m * PAD + ks * 8 + tg;
                int o1 = (m + 8) * PAD + ks * 8 + tg;
                ah[mt][0] = __float_as_uint(Ash[o0]);
                ah[mt][1] = __float_as_uint(Ash[o1]);
                ah[mt][2] = __float_as_uint(Ash[o0 + 4]);
                ah[mt][3] = __float_as_uint(Ash[o1 + 4]);
                al[mt][0] = __float_as_uint(Asl[o0]);
                al[mt][1] = __float_as_uint(Asl[o1]);
                al[mt][2] = __float_as_uint(Asl[o0 + 4]);
                al[mt][3] = __float_as_uint(Asl[o1 + 4]);
            }
            #pragma unroll
            for (int nt = 0; nt < 4; nt++) {
                int n = warpN + nt * 8 + g;
                int o = n * PAD + ks * 8 + tg;
                bh[nt][0] = __float_as_uint(Bsh[o]);
                bh[nt][1] = __float_as_uint(Bsh[o + 4]);
            }
            #pragma unroll
            for (int mt = 0; mt < 4; mt++)
                #pragma unroll
                for (int nt = 0; nt < 4; nt++) MMA_TF32(d[mt][nt], ah[mt], bh[nt]);
            #pragma unroll
            for (int mt = 0; mt < 4; mt++)
                #pragma unroll
                for (int nt = 0; nt < 4; nt++) MMA_TF32(d[mt][nt], al[mt], bh[nt]);
        }
        __syncthreads();
        if (++buf == 3) buf = 0;
    }

    // ---- epilogue: activation + mask + near-threshold flagging ----
    #pragma unroll
    for (int mt = 0; mt < 4; mt++) {
        int r0 = bm + warpM + mt * 16 + g;
        int r1 = r0 + 8;
        float rp0 = 1.0f / prob[r0];
        float rp1 = 1.0f / prob[r1];
        #pragma unroll
        for (int nt = 0; nt < 4; nt++) {
            int c = bn + warpN + nt * 8 + tg * 2;
            float2 o0, o1, m0, m1;
            #pragma unroll
            for (int q = 0; q < 4; q++) {
                float pre = d[mt][nt][q];
                int   rr  = (q < 2) ? r0 : r1;
                int   cc  = c + (q & 1);
                bool  gt  = pre > 0.6f;
                float act = (gt && pre <= 1.0f) ? pre : 1.0f;
                float rv  = act * ((q < 2) ? rp0 : rp1);
                float mv  = gt ? 1.0f : 0.0f;
                if (q == 0) { o0.x = rv; m0.x = mv; }
                else if (q == 1) { o0.y = rv; m0.y = mv; }
                else if (q == 2) { o1.x = rv; m1.x = mv; }
                else { o1.y = rv; m1.y = mv; }
                if (fabsf(pre - 0.6f) < DELTA) {
                    unsigned idx = atomicAdd(&gFixCnt, 1u);
                    if (idx < FIX_CAP)
                        gFix[idx] = ((unsigned)rr << 13) | (unsigned)cc;
                }
            }
            *(float2*)(outp  + (size_t)r0 * 8192 + c) = o0;
            *(float2*)(outp  + (size_t)r1 * 8192 + c) = o1;
            *(float2*)(maskp + (size_t)r0 * 8192 + c) = m0;
            *(float2*)(maskp + (size_t)r1 * 8192 + c) = m1;
        }
    }
}

// ---------------------------------------------------------------------------
// fixup (warp-per-element): lanes split the K=1024 dot, shfl-reduce fp32.
// Operands reconstructed exactly (hi+lo); coalesced 128B loads per array.
// ---------------------------------------------------------------------------
__global__ __launch_bounds__(256)
void fixup(float* __restrict__ outp, float* __restrict__ maskp,
           const float* __restrict__ prob)
{
    unsigned cnt = gFixCnt;
    if (cnt > FIX_CAP) cnt = FIX_CAP;
    const int lane   = threadIdx.x & 31;
    const unsigned warpId  = (blockIdx.x * blockDim.x + threadIdx.x) >> 5;
    const unsigned nWarps  = (gridDim.x * blockDim.x) >> 5;

    for (unsigned i = warpId; i < cnt; i += nWarps) {
        unsigned e = gFix[i];
        int m = e >> 13;
        int n = e & 8191;
        const float4* ath = (const float4*)(gTh + (size_t)m * KDIM);
        const float4* atl = (const float4*)(gTl + (size_t)m * KDIM);
        const float4* bth = (const float4*)(gBh + (size_t)n * KDIM);
        const float4* btl = (const float4*)(gBl + (size_t)n * KDIM);
        float s = 0.0f;
        #pragma unroll
        for (int j = 0; j < 8; j++) {
            int k = lane + j * 32;           // float4 index, coalesced per j
            float4 ah = ath[k], al = atl[k], bh = bth[k], bl = btl[k];
            s = fmaf(ah.x + al.x, bh.x + bl.x, s);
            s = fmaf(ah.y + al.y, bh.y + bl.y, s);
            s = fmaf(ah.z + al.z, bh.z + bl.z, s);
            s = fmaf(ah.w + al.w, bh.w + bl.w, s);
        }
        #pragma unroll
        for (int o = 16; o > 0; o >>= 1)
            s += __shfl_xor_sync(0xFFFFFFFFu, s, o);

        if (lane == 0) {
            bool  gt  = s > 0.6f;
            float act = (gt && s <= 1.0f) ? s : 1.0f;
            size_t off = (size_t)m * 8192 + n;
            outp[off]  = act * (1.0f / prob[m]);
            maskp[off] = gt ? 1.0f : 0.0f;
        }
    }
}

// ---------------------------------------------------------------------------
extern "C" void kernel_launch(void* const* d_in, const int* in_sizes, int n_in,
                              void* d_out, int out_size)
{
    const float* inputs = (const float*)d_in[0];   // [1024, 8192]
    const float* adj    = (const float*)d_in[1];   // [8192, 1024]
    const float* prob   = (const float*)d_in[2];   // [8192]
    const float* w      = (const float*)d_in[3];   // [1024, 1024]

    float* out  = (float*)d_out;
    float* mask = (float*)d_out + (size_t)8192 * 8192;

    cudaFuncSetAttribute(gemm2, cudaFuncAttributeMaxDynamicSharedMemorySize, SMEM_TOTAL);

    // inputs^T, split hi/lo (also zeroes fixup counter)
    tkern<<<dim3(256, 32), dim3(32, 8)>>>(inputs, 8192);

    // GEMM1 (fp32 SIMT): T = adj @ (w/17), epilogue splits to gTh/gTl
    sgemm1<<<dim3(1024 / BN, 8192 / BM), 256>>>(adj, w);

    // GEMM2 (2-term tf32): pre ~= T @ tf32(inputs), fused epilogue + flagging
    gemm2<<<dim3(8192 / BN, 8192 / BM), 256, SMEM_TOTAL>>>(out, mask, prob);

    // recompute near-threshold elements (warp-per-element, exact fp32 operands)
    fixup<<<1024, 256>>>(out, mask, prob);
}

// round 16
// speedup vs baseline: 1.8169x; 1.1660x over previous
#include <cuda_runtime.h>
#include <cuda_bf16.h>
#include <cstdint>
#include <cstddef>

// ============================================================================
// interAUGraphConv, GB300 (compute_103 PTX => no tcgen05; mma.sync bf16)
//
//   GEMM1: T[8192,1024]   = adj @ (w/17)     -- fp32 SIMT, sequential-k (exact)
//   GEMM2: pre[8192,8192] = T @ inputs       -- 3-term bf16 mma.sync m16n8k16:
//            T ~ a1+a2, B ~ b1+b2 (2-term bf16 splits, residual ~2^-18)
//            pre ~= a1b1 + a2b1 + a1b2       (dropped a2b2 ~ 1e-5 abs)
//   out = (0.6<pre<=1 ? pre : 1)/prob[row], mask = pre>0.6
//
// |pre-0.6| < DELTA  => recompute with the EXACT fp32 rows (gT, gBT) in the
// proven sequential-k order (bitwise round-13 fixup) -> no threshold flips.
// ============================================================================

static const int KDIM = 1024;
static const int BM = 128, BN = 128, BK = 16;

// gemm2 smem tile: 128 rows x 16 bf16 = 8 data u32/row, pad to 12 (bank-clean)
static const int ROW_U32   = 12;
static const int TILE_U32  = 128 * ROW_U32;        // 1536
static const int STAGE_U32 = 4 * TILE_U32;         // a1,a2,b1,b2 -> 6144
static const int STAGE_B   = STAGE_U32 * 4;        // 24576 bytes
static const int NSTAGE    = 4;
static const int SMEM_TOTAL = NSTAGE * STAGE_B;    // 98304 (2 CTAs/SM fit)

static const unsigned FIX_CAP = 1u << 22;
#define DELTA 5.0e-4f

// ---- device scratch ----
__device__ float gT [(size_t)8192 * 1024];                 // exact T (fixup)
__device__ float gBT[(size_t)8192 * 1024];                 // exact inputs^T (fixup)
__device__ __nv_bfloat16 gTb1[(size_t)8192 * 1024];        // bf16 hi(T)
__device__ __nv_bfloat16 gTb2[(size_t)8192 * 1024];        // bf16 lo(T)
__device__ __nv_bfloat16 gBb1[(size_t)8192 * 1024];        // bf16 hi(B^T)
__device__ __nv_bfloat16 gBb2[(size_t)8192 * 1024];        // bf16 lo(B^T)
__device__ unsigned gFixCnt;
__device__ unsigned gFix[FIX_CAP];

// ---------------------------------------------------------------------------
__device__ __forceinline__ uint32_t smem_u32(const void* p) {
    uint32_t a;
    asm("{ .reg .u64 t; cvta.to.shared.u64 t, %1; cvt.u32.u64 %0, t; }" : "=r"(a) : "l"(p));
    return a;
}
#define CP_ASYNC16(saddr, gptr) \
    asm volatile("cp.async.cg.shared.global [%0], [%1], 16;" :: "r"(saddr), "l"(gptr))
#define CP_COMMIT() asm volatile("cp.async.commit_group;" ::: "memory")
#define CP_WAIT2()  asm volatile("cp.async.wait_group 2;" ::: "memory")

#define MMA_BF16(d, a, b)                                                   \
    asm volatile(                                                           \
        "mma.sync.aligned.m16n8k16.row.col.f32.bf16.bf16.f32 "              \
        "{%0,%1,%2,%3}, {%4,%5,%6,%7}, {%8,%9}, {%0,%1,%2,%3};"             \
        : "+f"((d)[0]), "+f"((d)[1]), "+f"((d)[2]), "+f"((d)[3])            \
        : "r"((a)[0]), "r"((a)[1]), "r"((a)[2]), "r"((a)[3]),               \
          "r"((b)[0]), "r"((b)[1]))

__device__ __forceinline__ void bf16_split(float x, __nv_bfloat16& h, __nv_bfloat16& l) {
    h = __float2bfloat16(x);
    l = __float2bfloat16(x - __bfloat162float(h));
}

// ---------------------------------------------------------------------------
// transpose + split: inputs [1024, 8192] -> gBT (fp32) + gBb1/gBb2 (bf16)
// (also clears the fixup counter)
// ---------------------------------------------------------------------------
__global__ __launch_bounds__(256) void tkern(const float* __restrict__ in, int N) {
    __shared__ float t[32][33];
    if (blockIdx.x == 0 && blockIdx.y == 0 && threadIdx.x == 0 && threadIdx.y == 0)
        gFixCnt = 0;
    int n0 = blockIdx.x * 32, k0 = blockIdx.y * 32;
    int tx = threadIdx.x, ty = threadIdx.y;    // (32, 8)
    #pragma unroll
    for (int p = 0; p < 4; p++)
        t[ty + p * 8][tx] = in[(size_t)(k0 + ty + p * 8) * N + n0 + tx];
    __syncthreads();
    #pragma unroll
    for (int p = 0; p < 4; p++) {
        float x = t[tx][ty + p * 8];
        size_t o = (size_t)(n0 + ty + p * 8) * KDIM + k0 + tx;
        __nv_bfloat16 h, l;
        bf16_split(x, h, l);
        gBT[o]  = x;
        gBb1[o] = h;
        gBb2[o] = l;
    }
}

// ---------------------------------------------------------------------------
// GEMM1: fp32 SIMT sequential-k (exact); epilogue writes gT + bf16 splits
// ---------------------------------------------------------------------------
__global__ __launch_bounds__(256, 2)
void sgemm1(const float* __restrict__ A, const float* __restrict__ B)
{
    __shared__ float As[BK][BM + 4];
    __shared__ float Bs[BK][BN];

    const int tid = threadIdx.x;
    const int tx  = tid & 15;
    const int ty  = tid >> 4;
    const int bm  = blockIdx.y * BM;
    const int bn  = blockIdx.x * BN;
    const int K = 1024, N = 1024;
    const float bscale = 1.0f / 17.0f;

    const float* Ab = A + (size_t)bm * K;
    const float* Bb = B + bn;

    float acc[8][8];
    #pragma unroll
    for (int i = 0; i < 8; i++)
        #pragma unroll
        for (int j = 0; j < 8; j++) acc[i][j] = 0.0f;

    for (int k0 = 0; k0 < K; k0 += BK) {
        #pragma unroll
        for (int l = 0; l < 2; l++) {
            int i = tid + l * 256, row = i >> 2, kc = (i & 3) * 4;
            float4 v = *(const float4*)(Ab + (size_t)row * K + (k0 + kc));
            As[kc + 0][row] = v.x; As[kc + 1][row] = v.y;
            As[kc + 2][row] = v.z; As[kc + 3][row] = v.w;
        }
        #pragma unroll
        for (int l = 0; l < 2; l++) {
            int i = tid + l * 256, row = i >> 5, col = (i & 31) * 4;
            float4 v = *(const float4*)(Bb + (size_t)(k0 + row) * N + col);
            v.x *= bscale; v.y *= bscale; v.z *= bscale; v.w *= bscale;
            *(float4*)&Bs[row][col] = v;
        }
        __syncthreads();
        #pragma unroll
        for (int k = 0; k < BK; k++) {
            float regM[8], regN[8];
            *(float4*)&regM[0] = *(const float4*)&As[k][ty * 8];
            *(float4*)&regM[4] = *(const float4*)&As[k][ty * 8 + 4];
            *(float4*)&regN[0] = *(const float4*)&Bs[k][tx * 8];
            *(float4*)&regN[4] = *(const float4*)&Bs[k][tx * 8 + 4];
            #pragma unroll
            for (int i = 0; i < 8; i++)
                #pragma unroll
                for (int j = 0; j < 8; j++)
                    acc[i][j] += regM[i] * regN[j];
        }
        __syncthreads();
    }
    #pragma unroll
    for (int i = 0; i < 8; i++) {
        int r = bm + ty * 8 + i;
        #pragma unroll
        for (int jj = 0; jj < 8; jj += 4) {
            size_t off = (size_t)r * N + (bn + tx * 8 + jj);
            *(float4*)(gT + off) = *(const float4*)&acc[i][jj];
            __nv_bfloat16 h4[4], l4[4];
            #pragma unroll
            for (int q = 0; q < 4; q++) bf16_split(acc[i][jj + q], h4[q], l4[q]);
            *(uint2*)(gTb1 + off) = *(const uint2*)h4;
            *(uint2*)(gTb2 + off) = *(const uint2*)l4;
        }
    }
}

// ---------------------------------------------------------------------------
// GEMM2: 3-term bf16 m16n8k16 mma.sync + flagging epilogue
// smem stage: 4 tiles (a1, a2, b1, b2), each 128 rows x 8 data u32, stride 12
// ---------------------------------------------------------------------------
__device__ __forceinline__ void fill_stage2(uint32_t sm, int buf, int kc,
                                            int bm, int bn, int tid) {
    uint32_t base = sm + buf * STAGE_B;
    const __nv_bfloat16* srcs[4] = {
        gTb1 + (size_t)bm * KDIM, gTb2 + (size_t)bm * KDIM,
        gBb1 + (size_t)bn * KDIM, gBb2 + (size_t)bn * KDIM };
    #pragma unroll
    for (int t = 0; t < 4; t++) {
        int idx  = tid + t * 256;       // 0..1023
        int tile = idx >> 8;            // 0..3
        int r    = idx & 255;
        int row  = r >> 1;
        int half = r & 1;
        const __nv_bfloat16* g = srcs[tile] + (size_t)row * KDIM + kc * BK + half * 8;
        CP_ASYNC16(base + (uint32_t)(tile * (TILE_U32 * 4) + row * (ROW_U32 * 4) + half * 16), g);
    }
}

__global__ __launch_bounds__(256, 2)
void gemm2(float* __restrict__ outp, float* __restrict__ maskp,
           const float* __restrict__ prob)
{
    extern __shared__ uint32_t smem[];
    uint32_t sm = smem_u32(smem);

    const int tid  = threadIdx.x;
    const int w    = tid >> 5;
    const int lane = tid & 31;
    const int g    = lane >> 2;
    const int tg   = lane & 3;
    const int warpM = (w & 1) * 64;
    const int warpN = (w >> 1) * 32;
    const int bm = blockIdx.y * BM;
    const int bn = blockIdx.x * BN;

    float d[4][4][4];
    #pragma unroll
    for (int i = 0; i < 4; i++)
        #pragma unroll
        for (int j = 0; j < 4; j++)
            #pragma unroll
            for (int c = 0; c < 4; c++) d[i][j][c] = 0.0f;

    fill_stage2(sm, 0, 0, bm, bn, tid); CP_COMMIT();
    fill_stage2(sm, 1, 1, bm, bn, tid); CP_COMMIT();
    fill_stage2(sm, 2, 2, bm, bn, tid); CP_COMMIT();

    const int NCH = KDIM / BK;   // 64
    for (int i = 0; i < NCH; i++) {
        CP_WAIT2();               // stage i resident (<=2 younger pending)
        __syncthreads();
        int j = i + 3;
        if (j < NCH) fill_stage2(sm, (i + 3) & 3, j, bm, bn, tid);
        CP_COMMIT();

        const uint32_t* A1 = smem + (i & 3) * STAGE_U32;
        const uint32_t* A2 = A1 + TILE_U32;
        const uint32_t* B1 = A1 + 2 * TILE_U32;
        const uint32_t* B2 = A1 + 3 * TILE_U32;

        uint32_t a1[4][4], b1[4][2];
        #pragma unroll
        for (int mt = 0; mt < 4; mt++) {
            int m = warpM + mt * 16 + g;
            int o0 = m * ROW_U32 + tg;
            int o1 = (m + 8) * ROW_U32 + tg;
            a1[mt][0] = A1[o0];
            a1[mt][1] = A1[o1];
            a1[mt][2] = A1[o0 + 4];
            a1[mt][3] = A1[o1 + 4];
        }
        #pragma unroll
        for (int nt = 0; nt < 4; nt++) {
            int n = warpN + nt * 8 + g;
            int o = n * ROW_U32 + tg;
            b1[nt][0] = B1[o];
            b1[nt][1] = B1[o + 4];
        }
        // term 1: a1*b1
        #pragma unroll
        for (int mt = 0; mt < 4; mt++)
            #pragma unroll
            for (int nt = 0; nt < 4; nt++) MMA_BF16(d[mt][nt], a1[mt], b1[nt]);
        // term 2: a2*b1 (a2 transient)
        {
            uint32_t a2[4][4];
            #pragma unroll
            for (int mt = 0; mt < 4; mt++) {
                int m = warpM + mt * 16 + g;
                int o0 = m * ROW_U32 + tg;
                int o1 = (m + 8) * ROW_U32 + tg;
                a2[mt][0] = A2[o0];
                a2[mt][1] = A2[o1];
                a2[mt][2] = A2[o0 + 4];
                a2[mt][3] = A2[o1 + 4];
            }
            #pragma unroll
            for (int mt = 0; mt < 4; mt++)
                #pragma unroll
                for (int nt = 0; nt < 4; nt++) MMA_BF16(d[mt][nt], a2[mt], b1[nt]);
        }
        // term 3: a1*b2 (b2 transient)
        {
            uint32_t b2[4][2];
            #pragma unroll
            for (int nt = 0; nt < 4; nt++) {
                int n = warpN + nt * 8 + g;
                int o = n * ROW_U32 + tg;
                b2[nt][0] = B2[o];
                b2[nt][1] = B2[o + 4];
            }
            #pragma unroll
            for (int mt = 0; mt < 4; mt++)
                #pragma unroll
                for (int nt = 0; nt < 4; nt++) MMA_BF16(d[mt][nt], a1[mt], b2[nt]);
        }
        __syncthreads();
    }

    // ---- epilogue: activation + mask + near-threshold flagging ----
    #pragma unroll
    for (int mt = 0; mt < 4; mt++) {
        int r0 = bm + warpM + mt * 16 + g;
        int r1 = r0 + 8;
        float rp0 = 1.0f / prob[r0];
        float rp1 = 1.0f / prob[r1];
        #pragma unroll
        for (int nt = 0; nt < 4; nt++) {
            int c = bn + warpN + nt * 8 + tg * 2;
            float2 o0, o1, m0, m1;
            #pragma unroll
            for (int q = 0; q < 4; q++) {
                float pre = d[mt][nt][q];
                int   rr  = (q < 2) ? r0 : r1;
                int   cc  = c + (q & 1);
                bool  gt  = pre > 0.6f;
                float act = (gt && pre <= 1.0f) ? pre : 1.0f;
                float rv  = act * ((q < 2) ? rp0 : rp1);
                float mv  = gt ? 1.0f : 0.0f;
                if (q == 0) { o0.x = rv; m0.x = mv; }
                else if (q == 1) { o0.y = rv; m0.y = mv; }
                else if (q == 2) { o1.x = rv; m1.x = mv; }
                else { o1.y = rv; m1.y = mv; }
                if (fabsf(pre - 0.6f) < DELTA) {
                    unsigned idx = atomicAdd(&gFixCnt, 1u);
                    if (idx < FIX_CAP)
                        gFix[idx] = ((unsigned)rr << 13) | (unsigned)cc;
                }
            }
            *(float2*)(outp  + (size_t)r0 * 8192 + c) = o0;
            *(float2*)(outp  + (size_t)r1 * 8192 + c) = o1;
            *(float2*)(maskp + (size_t)r0 * 8192 + c) = m0;
            *(float2*)(maskp + (size_t)r1 * 8192 + c) = m1;
        }
    }
}

// ---------------------------------------------------------------------------
// fixup: warp stages exact fp32 rows into smem (coalesced), lane 0 then runs
// the sequential-k fp32 chain in the PROVEN reference-matching order.
// ---------------------------------------------------------------------------
__global__ __launch_bounds__(128)
void fixup(float* __restrict__ outp, float* __restrict__ maskp,
           const float* __restrict__ prob)
{
    __shared__ float rows[4][2048];           // per-warp: T row | B row
    unsigned cnt = gFixCnt;
    if (cnt > FIX_CAP) cnt = FIX_CAP;
    const int w    = threadIdx.x >> 5;
    const int lane = threadIdx.x & 31;
    const unsigned warpId = (blockIdx.x * blockDim.x + threadIdx.x) >> 5;
    const unsigned nWarps = (gridDim.x * blockDim.x) >> 5;

    float4* sr = (float4*)rows[w];            // [0..255]=T, [256..511]=B

    for (unsigned i = warpId; i < cnt; i += nWarps) {
        unsigned e = gFix[i];
        int m = e >> 13;
        int n = e & 8191;
        const float4* a = (const float4*)(gT  + (size_t)m * KDIM);
        const float4* b = (const float4*)(gBT + (size_t)n * KDIM);
        #pragma unroll
        for (int j = 0; j < 8; j++) {
            sr[lane + 32 * j]       = a[lane + 32 * j];
            sr[256 + lane + 32 * j] = b[lane + 32 * j];
        }
        __syncwarp();
        if (lane == 0) {
            float s = 0.0f;
            #pragma unroll 8
            for (int k = 0; k < 256; k++) {
                float4 av = sr[k], bv = sr[256 + k];
                s = fmaf(av.x, bv.x, s);
                s = fmaf(av.y, bv.y, s);
                s = fmaf(av.z, bv.z, s);
                s = fmaf(av.w, bv.w, s);
            }
            bool  gt  = s > 0.6f;
            float act = (gt && s <= 1.0f) ? s : 1.0f;
            size_t off = (size_t)m * 8192 + n;
            outp[off]  = act * (1.0f / prob[m]);
            maskp[off] = gt ? 1.0f : 0.0f;
        }
        __syncwarp();
    }
}

// ---------------------------------------------------------------------------
extern "C" void kernel_launch(void* const* d_in, const int* in_sizes, int n_in,
                              void* d_out, int out_size)
{
    const float* inputs = (const float*)d_in[0];   // [1024, 8192]
    const float* adj    = (const float*)d_in[1];   // [8192, 1024]
    const float* prob   = (const float*)d_in[2];   // [8192]
    const float* w      = (const float*)d_in[3];   // [1024, 1024]

    float* out  = (float*)d_out;
    float* mask = (float*)d_out + (size_t)8192 * 8192;

    cudaFuncSetAttribute(gemm2, cudaFuncAttributeMaxDynamicSharedMemorySize, SMEM_TOTAL);

    // inputs^T: exact fp32 + bf16 splits (also zeroes fixup counter)
    tkern<<<dim3(256, 32), dim3(32, 8)>>>(inputs, 8192);

    // GEMM1 (exact fp32 SIMT): T = adj @ (w/17); epilogue emits gT + splits
    sgemm1<<<dim3(1024 / BN, 8192 / BM), 256>>>(adj, w);

    // GEMM2 (3-term bf16 tensor): pre ~= T @ inputs, fused epilogue + flagging
    gemm2<<<dim3(8192 / BN, 8192 / BM), 256, SMEM_TOTAL>>>(out, mask, prob);

    // recompute near-threshold elements in exact sequential-order fp32
    fixup<<<512, 128>>>(out, mask, prob);
}

// round 17
// speedup vs baseline: 1.8416x; 1.0136x over previous
#include <cuda_runtime.h>
#include <cuda_bf16.h>
#include <cstdint>
#include <cstddef>

// ============================================================================
// interAUGraphConv, GB300 (compute_103 PTX => no tcgen05; mma.sync bf16)
//
//   prep (fused): GEMM1 T = adj @ (w/17) in packed-fp32 (fma.rn.f32x2,
//                 bitwise-identical per-element sequential-k chains)
//                 + transpose/split of inputs (fills the 2nd CTA slot/SM)
//   GEMM2: pre = T @ inputs  -- 3-term bf16 mma.sync m16n8k16
//            T ~ a1+a2, B ~ b1+b2 (2-term bf16 splits)
//            pre ~= a1b1 + a2b1 + a1b2   (dropped a2b2 ~ 1e-5 abs)
//   out = (0.6<pre<=1 ? pre : 1)/prob[row], mask = pre>0.6
//
// |pre-0.6| < DELTA => recompute with EXACT fp32 rows (gT, gBT) in the proven
// sequential-k order -> no threshold flips.
// ============================================================================

static const int KDIM = 1024;
static const int BM = 128, BN = 128, BK = 16;

// gemm2 smem tile: 128 rows x 16 bf16 = 8 data u32/row, pad to 12 (bank-clean)
static const int ROW_U32   = 12;
static const int TILE_U32  = 128 * ROW_U32;        // 1536
static const int STAGE_U32 = 4 * TILE_U32;         // a1,a2,b1,b2 -> 6144
static const int STAGE_B   = STAGE_U32 * 4;        // 24576 bytes
static const int NSTAGE    = 4;
static const int SMEM_TOTAL = NSTAGE * STAGE_B;    // 98304 (2 CTAs/SM fit)

static const unsigned FIX_CAP = 1u << 22;
#define DELTA 5.0e-4f

// ---- device scratch ----
__device__ float gT [(size_t)8192 * 1024];                 // exact T (fixup)
__device__ float gBT[(size_t)8192 * 1024];                 // exact inputs^T (fixup)
__device__ __nv_bfloat16 gTb1[(size_t)8192 * 1024];        // bf16 hi(T)
__device__ __nv_bfloat16 gTb2[(size_t)8192 * 1024];        // bf16 lo(T)
__device__ __nv_bfloat16 gBb1[(size_t)8192 * 1024];        // bf16 hi(B^T)
__device__ __nv_bfloat16 gBb2[(size_t)8192 * 1024];        // bf16 lo(B^T)
__device__ unsigned gFixCnt;
__device__ unsigned gFix[FIX_CAP];

// ---------------------------------------------------------------------------
__device__ __forceinline__ uint32_t smem_u32(const void* p) {
    uint32_t a;
    asm("{ .reg .u64 t; cvta.to.shared.u64 t, %1; cvt.u32.u64 %0, t; }" : "=r"(a) : "l"(p));
    return a;
}
#define CP_ASYNC16(saddr, gptr) \
    asm volatile("cp.async.cg.shared.global [%0], [%1], 16;" :: "r"(saddr), "l"(gptr))
#define CP_COMMIT() asm volatile("cp.async.commit_group;" ::: "memory")
#define CP_WAIT2()  asm volatile("cp.async.wait_group 2;" ::: "memory")

#define MMA_BF16(d, a, b)                                                   \
    asm volatile(                                                           \
        "mma.sync.aligned.m16n8k16.row.col.f32.bf16.bf16.f32 "              \
        "{%0,%1,%2,%3}, {%4,%5,%6,%7}, {%8,%9}, {%0,%1,%2,%3};"             \
        : "+f"((d)[0]), "+f"((d)[1]), "+f"((d)[2]), "+f"((d)[3])            \
        : "r"((a)[0]), "r"((a)[1]), "r"((a)[2]), "r"((a)[3]),               \
          "r"((b)[0]), "r"((b)[1]))

// packed fp32: d.lo += a.lo*b.lo, d.hi += a.hi*b.hi (independent fp32 fmas)
#define FMA_F32X2(d, a, b) \
    asm("fma.rn.f32x2 %0, %1, %2, %0;" : "+l"(d) : "l"(a), "l"(b))
#define PACK_DUP(d, x) \
    asm("mov.b64 %0, {%1, %1};" : "=l"(d) : "f"(x))
#define UNPACK2(lo, hi, v) \
    asm("mov.b64 {%0, %1}, %2;" : "=f"(lo), "=f"(hi) : "l"(v))

__device__ __forceinline__ void bf16_split(float x, __nv_bfloat16& h, __nv_bfloat16& l) {
    h = __float2bfloat16(x);
    l = __float2bfloat16(x - __bfloat162float(h));
}

// ---------------------------------------------------------------------------
// prep: fused GEMM1 (blocks 0..511) + inputs transpose/split (blocks 512..8703)
// ---------------------------------------------------------------------------
__global__ __launch_bounds__(256, 2)
void prep(const float* __restrict__ adj, const float* __restrict__ w,
          const float* __restrict__ inputs)
{
    __shared__ float sh[16 * 132 + 16 * 128];   // gemm1: As|Bs ; transpose: t
    const int tid = threadIdx.x;

    if (blockIdx.x >= 512) {
        // ---- transpose + split path: inputs[1024,8192] -> gBT/gBb1/gBb2 ----
        int tb = (int)blockIdx.x - 512;
        if (tb == 0 && tid == 0) gFixCnt = 0;
        float (*t)[33] = reinterpret_cast<float(*)[33]>(sh);
        int n0 = (tb & 255) * 32, k0 = (tb >> 8) * 32;
        int tx = tid & 31, ty = tid >> 5;          // 32 x 8
        const int N = 8192;
        #pragma unroll
        for (int p = 0; p < 4; p++)
            t[ty + p * 8][tx] = inputs[(size_t)(k0 + ty + p * 8) * N + n0 + tx];
        __syncthreads();
        #pragma unroll
        for (int p = 0; p < 4; p++) {
            float x = t[tx][ty + p * 8];
            size_t o = (size_t)(n0 + ty + p * 8) * KDIM + k0 + tx;
            __nv_bfloat16 h, l;
            bf16_split(x, h, l);
            gBT[o]  = x;
            gBb1[o] = h;
            gBb2[o] = l;
        }
        return;
    }

    // ---- GEMM1 path: T = adj @ (w/17), packed-fp32 fma ----
    float (*As)[BM + 4] = reinterpret_cast<float(*)[BM + 4]>(sh);
    float (*Bs)[BN]     = reinterpret_cast<float(*)[BN]>(sh + 16 * 132);

    const int tx  = tid & 15;
    const int ty  = tid >> 4;
    const int bm  = ((int)blockIdx.x >> 3) * BM;
    const int bn  = ((int)blockIdx.x & 7) * BN;
    const int K = 1024, N = 1024;
    const float bscale = 1.0f / 17.0f;

    const float* Ab = adj + (size_t)bm * K;
    const float* Bb = w + bn;

    unsigned long long accd[8][4];    // 8 rows x 4 col-pairs, packed f32x2
    #pragma unroll
    for (int i = 0; i < 8; i++)
        #pragma unroll
        for (int j = 0; j < 4; j++) accd[i][j] = 0ull;

    for (int k0 = 0; k0 < K; k0 += BK) {
        #pragma unroll
        for (int l = 0; l < 2; l++) {
            int i = tid + l * 256, row = i >> 2, kc = (i & 3) * 4;
            float4 v = *(const float4*)(Ab + (size_t)row * K + (k0 + kc));
            As[kc + 0][row] = v.x; As[kc + 1][row] = v.y;
            As[kc + 2][row] = v.z; As[kc + 3][row] = v.w;
        }
        #pragma unroll
        for (int l = 0; l < 2; l++) {
            int i = tid + l * 256, row = i >> 5, col = (i & 31) * 4;
            float4 v = *(const float4*)(Bb + (size_t)(k0 + row) * N + col);
            v.x *= bscale; v.y *= bscale; v.z *= bscale; v.w *= bscale;
            *(float4*)&Bs[row][col] = v;
        }
        __syncthreads();
        #pragma unroll
        for (int k = 0; k < BK; k++) {
            float regM[8];
            *(float4*)&regM[0] = *(const float4*)&As[k][ty * 8];
            *(float4*)&regM[4] = *(const float4*)&As[k][ty * 8 + 4];
            float4 b0 = *(const float4*)&Bs[k][tx * 8];
            float4 b1 = *(const float4*)&Bs[k][tx * 8 + 4];
            unsigned long long bp[4];
            PACK_DUP(bp[0], b0.x);  // overwritten below; placeholder init
            asm("mov.b64 %0, {%1, %2};" : "=l"(bp[0]) : "f"(b0.x), "f"(b0.y));
            asm("mov.b64 %0, {%1, %2};" : "=l"(bp[1]) : "f"(b0.z), "f"(b0.w));
            asm("mov.b64 %0, {%1, %2};" : "=l"(bp[2]) : "f"(b1.x), "f"(b1.y));
            asm("mov.b64 %0, {%1, %2};" : "=l"(bp[3]) : "f"(b1.z), "f"(b1.w));
            #pragma unroll
            for (int i = 0; i < 8; i++) {
                unsigned long long am;
                PACK_DUP(am, regM[i]);
                #pragma unroll
                for (int jp = 0; jp < 4; jp++)
                    FMA_F32X2(accd[i][jp], am, bp[jp]);
            }
        }
        __syncthreads();
    }

    #pragma unroll
    for (int i = 0; i < 8; i++) {
        int r = bm + ty * 8 + i;
        float acc[8];
        #pragma unroll
        for (int jp = 0; jp < 4; jp++)
            UNPACK2(acc[2 * jp], acc[2 * jp + 1], accd[i][jp]);
        #pragma unroll
        for (int jj = 0; jj < 8; jj += 4) {
            size_t off = (size_t)r * N + (bn + tx * 8 + jj);
            *(float4*)(gT + off) = *(const float4*)&acc[jj];
            __nv_bfloat16 h4[4], l4[4];
            #pragma unroll
            for (int q = 0; q < 4; q++) bf16_split(acc[jj + q], h4[q], l4[q]);
            *(uint2*)(gTb1 + off) = *(const uint2*)h4;
            *(uint2*)(gTb2 + off) = *(const uint2*)l4;
        }
    }
}

// ---------------------------------------------------------------------------
// GEMM2: 3-term bf16 m16n8k16 mma.sync + flagging epilogue
// ---------------------------------------------------------------------------
__device__ __forceinline__ void fill_stage2(uint32_t sm, int buf, int kc,
                                            int bm, int bn, int tid) {
    uint32_t base = sm + buf * STAGE_B;
    const __nv_bfloat16* srcs[4] = {
        gTb1 + (size_t)bm * KDIM, gTb2 + (size_t)bm * KDIM,
        gBb1 + (size_t)bn * KDIM, gBb2 + (size_t)bn * KDIM };
    #pragma unroll
    for (int t = 0; t < 4; t++) {
        int idx  = tid + t * 256;       // 0..1023
        int tile = idx >> 8;            // 0..3
        int r    = idx & 255;
        int row  = r >> 1;
        int half = r & 1;
        const __nv_bfloat16* g = srcs[tile] + (size_t)row * KDIM + kc * BK + half * 8;
        CP_ASYNC16(base + (uint32_t)(tile * (TILE_U32 * 4) + row * (ROW_U32 * 4) + half * 16), g);
    }
}

__global__ __launch_bounds__(256, 2)
void gemm2(float* __restrict__ outp, float* __restrict__ maskp,
           const float* __restrict__ prob)
{
    extern __shared__ uint32_t smem[];
    uint32_t sm = smem_u32(smem);

    const int tid  = threadIdx.x;
    const int w    = tid >> 5;
    const int lane = tid & 31;
    const int g    = lane >> 2;
    const int tg   = lane & 3;
    const int warpM = (w & 1) * 64;
    const int warpN = (w >> 1) * 32;
    const int bm = blockIdx.y * BM;
    const int bn = blockIdx.x * BN;

    float d[4][4][4];
    #pragma unroll
    for (int i = 0; i < 4; i++)
        #pragma unroll
        for (int j = 0; j < 4; j++)
            #pragma unroll
            for (int c = 0; c < 4; c++) d[i][j][c] = 0.0f;

    fill_stage2(sm, 0, 0, bm, bn, tid); CP_COMMIT();
    fill_stage2(sm, 1, 1, bm, bn, tid); CP_COMMIT();
    fill_stage2(sm, 2, 2, bm, bn, tid); CP_COMMIT();

    const int NCH = KDIM / BK;   // 64
    for (int i = 0; i < NCH; i++) {
        CP_WAIT2();               // stage i resident (<=2 younger pending)
        __syncthreads();          // also: everyone done reading stage i-1
        int j = i + 3;            // fill buf (i+3)&3 == (i-1)&3, safe after bar
        if (j < NCH) fill_stage2(sm, j & 3, j, bm, bn, tid);
        CP_COMMIT();

        const uint32_t* A1 = smem + (i & 3) * STAGE_U32;
        const uint32_t* A2 = A1 + TILE_U32;
        const uint32_t* B1 = A1 + 2 * TILE_U32;
        const uint32_t* B2 = A1 + 3 * TILE_U32;

        uint32_t a1[4][4], b1[4][2];
        #pragma unroll
        for (int mt = 0; mt < 4; mt++) {
            int m = warpM + mt * 16 + g;
            int o0 = m * ROW_U32 + tg;
            int o1 = (m + 8) * ROW_U32 + tg;
            a1[mt][0] = A1[o0];
            a1[mt][1] = A1[o1];
            a1[mt][2] = A1[o0 + 4];
            a1[mt][3] = A1[o1 + 4];
        }
        #pragma unroll
        for (int nt = 0; nt < 4; nt++) {
            int n = warpN + nt * 8 + g;
            int o = n * ROW_U32 + tg;
            b1[nt][0] = B1[o];
            b1[nt][1] = B1[o + 4];
        }
        // term 1: a1*b1
        #pragma unroll
        for (int mt = 0; mt < 4; mt++)
            #pragma unroll
            for (int nt = 0; nt < 4; nt++) MMA_BF16(d[mt][nt], a1[mt], b1[nt]);
        // term 2: a2*b1
        {
            uint32_t a2[4][4];
            #pragma unroll
            for (int mt = 0; mt < 4; mt++) {
                int m = warpM + mt * 16 + g;
                int o0 = m * ROW_U32 + tg;
                int o1 = (m + 8) * ROW_U32 + tg;
                a2[mt][0] = A2[o0];
                a2[mt][1] = A2[o1];
                a2[mt][2] = A2[o0 + 4];
                a2[mt][3] = A2[o1 + 4];
            }
            #pragma unroll
            for (int mt = 0; mt < 4; mt++)
                #pragma unroll
                for (int nt = 0; nt < 4; nt++) MMA_BF16(d[mt][nt], a2[mt], b1[nt]);
        }
        // term 3: a1*b2
        {
            uint32_t b2[4][2];
            #pragma unroll
            for (int nt = 0; nt < 4; nt++) {
                int n = warpN + nt * 8 + g;
                int o = n * ROW_U32 + tg;
                b2[nt][0] = B2[o];
                b2[nt][1] = B2[o + 4];
            }
            #pragma unroll
            for (int mt = 0; mt < 4; mt++)
                #pragma unroll
                for (int nt = 0; nt < 4; nt++) MMA_BF16(d[mt][nt], a1[mt], b2[nt]);
        }
        // no trailing __syncthreads: next iter's top barrier protects buf reuse
    }

    // ---- epilogue: activation + mask + near-threshold flagging ----
    #pragma unroll
    for (int mt = 0; mt < 4; mt++) {
        int r0 = bm + warpM + mt * 16 + g;
        int r1 = r0 + 8;
        float rp0 = 1.0f / prob[r0];
        float rp1 = 1.0f / prob[r1];
        #pragma unroll
        for (int nt = 0; nt < 4; nt++) {
            int c = bn + warpN + nt * 8 + tg * 2;
            float2 o0, o1, m0, m1;
            #pragma unroll
            for (int q = 0; q < 4; q++) {
                float pre = d[mt][nt][q];
                int   rr  = (q < 2) ? r0 : r1;
                int   cc  = c + (q & 1);
                bool  gt  = pre > 0.6f;
                float act = (gt && pre <= 1.0f) ? pre : 1.0f;
                float rv  = act * ((q < 2) ? rp0 : rp1);
                float mv  = gt ? 1.0f : 0.0f;
                if (q == 0) { o0.x = rv; m0.x = mv; }
                else if (q == 1) { o0.y = rv; m0.y = mv; }
                else if (q == 2) { o1.x = rv; m1.x = mv; }
                else { o1.y = rv; m1.y = mv; }
                if (fabsf(pre - 0.6f) < DELTA) {
                    unsigned idx = atomicAdd(&gFixCnt, 1u);
                    if (idx < FIX_CAP)
                        gFix[idx] = ((unsigned)rr << 13) | (unsigned)cc;
                }
            }
            *(float2*)(outp  + (size_t)r0 * 8192 + c) = o0;
            *(float2*)(outp  + (size_t)r1 * 8192 + c) = o1;
            *(float2*)(maskp + (size_t)r0 * 8192 + c) = m0;
            *(float2*)(maskp + (size_t)r1 * 8192 + c) = m1;
        }
    }
}

// ---------------------------------------------------------------------------
// fixup: warp stages exact fp32 rows into smem (coalesced), lane 0 then runs
// the sequential-k fp32 chain in the PROVEN reference-matching order.
// ---------------------------------------------------------------------------
__global__ __launch_bounds__(128)
void fixup(float* __restrict__ outp, float* __restrict__ maskp,
           const float* __restrict__ prob)
{
    __shared__ float rows[4][2048];           // per-warp: T row | B row
    unsigned cnt = gFixCnt;
    if (cnt > FIX_CAP) cnt = FIX_CAP;
    const int w    = threadIdx.x >> 5;
    const int lane = threadIdx.x & 31;
    const unsigned warpId = (blockIdx.x * blockDim.x + threadIdx.x) >> 5;
    const unsigned nWarps = (gridDim.x * blockDim.x) >> 5;

    float4* sr = (float4*)rows[w];            // [0..255]=T, [256..511]=B

    for (unsigned i = warpId; i < cnt; i += nWarps) {
        unsigned e = gFix[i];
        int m = e >> 13;
        int n = e & 8191;
        const float4* a = (const float4*)(gT  + (size_t)m * KDIM);
        const float4* b = (const float4*)(gBT + (size_t)n * KDIM);
        #pragma unroll
        for (int j = 0; j < 8; j++) {
            sr[lane + 32 * j]       = a[lane + 32 * j];
            sr[256 + lane + 32 * j] = b[lane + 32 * j];
        }
        __syncwarp();
        if (lane == 0) {
            float s = 0.0f;
            #pragma unroll 8
            for (int k = 0; k < 256; k++) {
                float4 av = sr[k], bv = sr[256 + k];
                s = fmaf(av.x, bv.x, s);
                s = fmaf(av.y, bv.y, s);
                s = fmaf(av.z, bv.z, s);
                s = fmaf(av.w, bv.w, s);
            }
            bool  gt  = s > 0.6f;
            float act = (gt && s <= 1.0f) ? s : 1.0f;
            size_t off = (size_t)m * 8192 + n;
            outp[off]  = act * (1.0f / prob[m]);
            maskp[off] = gt ? 1.0f : 0.0f;
        }
        __syncwarp();
    }
}

// ---------------------------------------------------------------------------
extern "C" void kernel_launch(void* const* d_in, const int* in_sizes, int n_in,
                              void* d_out, int out_size)
{
    const float* inputs = (const float*)d_in[0];   // [1024, 8192]
    const float* adj    = (const float*)d_in[1];   // [8192, 1024]
    const float* prob   = (const float*)d_in[2];   // [8192]
    const float* w      = (const float*)d_in[3];   // [1024, 1024]

    float* out  = (float*)d_out;
    float* mask = (float*)d_out + (size_t)8192 * 8192;

    cudaFuncSetAttribute(gemm2, cudaFuncAttributeMaxDynamicSharedMemorySize, SMEM_TOTAL);

    // fused: GEMM1 (packed-fp32, blocks 0..511) + transpose/split (512..8703)
    prep<<<8704, 256>>>(adj, w, inputs);

    // GEMM2 (3-term bf16 tensor): pre ~= T @ inputs, fused epilogue + flagging
    gemm2<<<dim3(8192 / BN, 8192 / BM), 256, SMEM_TOTAL>>>(out, mask, prob);

    // recompute near-threshold elements in exact sequential-order fp32
    fixup<<<512, 128>>>(out, mask, prob);
}